// round 13
// baseline (speedup 1.0000x reference)
#include <cuda_runtime.h>
#include <cuda_fp16.h>
#include <cstdint>
#include <cstdio>

#define HID   1024
#define CDIM  1024
#define NHEAD 16
#define HDIM  64
#define LSEQ  2048
#define BATCH 2
#define MTOT  4096   // B*L
#define MLPD  4096

// ---------------- scratch (static device globals; no cudaMalloc allowed) ---
__device__ __half g_normed[MTOT * HID];
__device__ __half g_q[MTOT * HID];
__device__ __half g_k[MTOT * HID];
__device__ __half g_v[MTOT * HID];
__device__ __half g_attn[MTOT * HID];
__device__ __half g_h[MTOT * MLPD];
__device__ float  g_ss[2 * BATCH * 2048];   // [layer][batch][2H]
// fp16 pre-converted weights
__device__ __half g_rwq[HID * HID];
__device__ __half g_rwk[HID * HID];
__device__ __half g_rwv[HID * HID];
__device__ __half g_rwo[HID * HID];
__device__ __half g_rw1[MLPD * HID];
__device__ __half g_rw2[HID * MLPD];

// ---------------- helpers --------------------------------------------------
__device__ __forceinline__ void mma16(float* d, const uint32_t* a,
                                      uint32_t b0, uint32_t b1) {
    asm volatile(
        "mma.sync.aligned.m16n8k16.row.col.f32.f16.f16.f32 "
        "{%0,%1,%2,%3}, {%4,%5,%6,%7}, {%8,%9}, {%0,%1,%2,%3};\n"
        : "+f"(d[0]), "+f"(d[1]), "+f"(d[2]), "+f"(d[3])
        : "r"(a[0]), "r"(a[1]), "r"(a[2]), "r"(a[3]), "r"(b0), "r"(b1));
}

__device__ __forceinline__ void ldsm4(uint32_t* r, uint32_t addr) {
    asm volatile("ldmatrix.sync.aligned.m8n8.x4.shared.b16 {%0,%1,%2,%3}, [%4];"
        : "=r"(r[0]), "=r"(r[1]), "=r"(r[2]), "=r"(r[3]) : "r"(addr));
}

__device__ __forceinline__ void ldsm4t(uint32_t* r, uint32_t addr) {
    asm volatile("ldmatrix.sync.aligned.m8n8.x4.trans.shared.b16 {%0,%1,%2,%3}, [%4];"
        : "=r"(r[0]), "=r"(r[1]), "=r"(r[2]), "=r"(r[3]) : "r"(addr));
}

__device__ __forceinline__ void cpasync16(uint32_t dst, const void* src) {
    asm volatile("cp.async.cg.shared.global [%0], [%1], 16;" :: "r"(dst), "l"(src));
}

__device__ __forceinline__ void store2(float* p, float a, float b) {
    *(float2*)p = make_float2(a, b);
}
__device__ __forceinline__ void store2(__half* p, float a, float b) {
    *(half2*)p = __floats2half2_rn(a, b);
}

// ---------------- fused prep: weight fp16 conversion + adaLN modulation ----
// blocks [0, 12288): convert 6 weight matrices fp32->fp16
// blocks [12288, 13312): ss = cond @ W_adaln^T + b  (both layers)
__global__ void __launch_bounds__(256) prep_kernel(
    const float* __restrict__ wq, const float* __restrict__ wk,
    const float* __restrict__ wv, const float* __restrict__ wo,
    const float* __restrict__ w1, const float* __restrict__ w2,
    __half* __restrict__ rq, __half* __restrict__ rk,
    __half* __restrict__ rv, __half* __restrict__ ro,
    __half* __restrict__ r1, __half* __restrict__ r2,
    const float* __restrict__ cond,
    const float* __restrict__ wa1, const float* __restrict__ ba1,
    const float* __restrict__ wa2, const float* __restrict__ ba2,
    float* __restrict__ ss)
{
    if (blockIdx.x < 12288) {
        const int S = 262144; // 1M floats in float4 units
        int idx = blockIdx.x * 256 + threadIdx.x;  // 0 .. 3145727
        const float* s; __half* d; int off;
        if      (idx <     S) { s = wq; d = rq; off = idx; }
        else if (idx < 2 * S) { s = wk; d = rk; off = idx - S; }
        else if (idx < 3 * S) { s = wv; d = rv; off = idx - 2 * S; }
        else if (idx < 4 * S) { s = wo; d = ro; off = idx - 3 * S; }
        else if (idx < 8 * S) { s = w1; d = r1; off = idx - 4 * S; }
        else                  { s = w2; d = r2; off = idx - 8 * S; }
        float4 v = ((const float4*)s)[off];
        half2 h01 = __floats2half2_rn(v.x, v.y);
        half2 h23 = __floats2half2_rn(v.z, v.w);
        ((half2*)d)[off * 2]     = h01;
        ((half2*)d)[off * 2 + 1] = h23;
    } else {
        int warp = threadIdx.x >> 5, lane = threadIdx.x & 31;
        int gw = (blockIdx.x - 12288) * 8 + warp;  // 0..8191
        int layer = gw >> 12;
        int rem = gw & 4095;
        int b = rem >> 11;
        int row = rem & 2047;
        const float* W  = layer ? wa2 : wa1;
        const float* bv = layer ? ba2 : ba1;
        const float* c  = cond + b * CDIM;
        const float* wr = W + (size_t)row * CDIM;
        float s = 0.f;
        for (int k = lane; k < CDIM; k += 32) s += c[k] * wr[k];
        #pragma unroll
        for (int o = 16; o > 0; o >>= 1) s += __shfl_xor_sync(0xffffffffu, s, o);
        if (lane == 0) ss[layer * (BATCH * 2048) + b * 2048 + row] = s + bv[row];
    }
}

// ---------------- LayerNorm * (1+scale) + shift (output fp16) --------------
__global__ void __launch_bounds__(256) adaln_kernel(
    const float* __restrict__ x, const float* __restrict__ ss,
    __half* __restrict__ out)
{
    int row = blockIdx.x;
    int b = row >> 11;
    const float* xr = x + (size_t)row * HID;
    float v[4];
    float s = 0.f, sq = 0.f;
    #pragma unroll
    for (int i = 0; i < 4; i++) {
        v[i] = xr[threadIdx.x + i * 256];
        s += v[i];
        sq += v[i] * v[i];
    }
    __shared__ float red[16];
    #pragma unroll
    for (int o = 16; o > 0; o >>= 1) {
        s  += __shfl_xor_sync(0xffffffffu, s,  o);
        sq += __shfl_xor_sync(0xffffffffu, sq, o);
    }
    int warp = threadIdx.x >> 5, lane = threadIdx.x & 31;
    if (lane == 0) { red[warp] = s; red[warp + 8] = sq; }
    __syncthreads();
    if (warp == 0) {
        float a  = lane < 8 ? red[lane] : 0.f;
        float c2 = lane < 8 ? red[lane + 8] : 0.f;
        #pragma unroll
        for (int o = 4; o > 0; o >>= 1) {
            a  += __shfl_xor_sync(0xffffffffu, a,  o);
            c2 += __shfl_xor_sync(0xffffffffu, c2, o);
        }
        if (lane == 0) { red[0] = a; red[1] = c2; }
    }
    __syncthreads();
    float mean = red[0] * (1.f / HID);
    float var  = red[1] * (1.f / HID) - mean * mean;
    float rs   = rsqrtf(var + 1e-5f);
    const float* sc = ss + b * 2048;
    #pragma unroll
    for (int i = 0; i < 4; i++) {
        int c = threadIdx.x + i * 256;
        out[(size_t)row * HID + c] =
            __float2half_rn((v[i] - mean) * rs * (1.f + sc[c]) + sc[1024 + c]);
    }
}

// ---------------- pipelined FP16 GEMM: C = A @ B^T + bias (+resid)(gelu) ---
// A [M,K] half row-major, B [N,K] half row-major (weight).
// BN=128, BK=64 halves (128B rows), 256 threads = 8 warps as 4x2.
// TBMT=128: warp tile 32x64, 2 CTAs/SM (R12-proven).
// TBMT=64:  warp tile 16x64, 3 CTAs/SM — finer M-tiles for grid-starved
//           GEMMs (O-proj, MLP2): 512 CTAs -> balanced SM load.
// 3-stage cp.async ring, XOR-swizzled smem, ldmatrix frags.
// blockIdx.z selects (B,bias,C) for fused QKV.
#define TBN 128
#define TBK 64
#define GSTAGES 3

template <bool GELU, bool RESID, typename OT, int TBMT>
__global__ void __launch_bounds__(256, (TBMT == 128) ? 2 : 3) gemm2(
    const __half* __restrict__ A,
    const __half* __restrict__ Bp0, const __half* __restrict__ Bp1, const __half* __restrict__ Bp2,
    const float* __restrict__ bias0, const float* __restrict__ bias1, const float* __restrict__ bias2,
    const float* __restrict__ R,
    OT* __restrict__ C0, OT* __restrict__ C1, OT* __restrict__ C2,
    int M, int N, int K)
{
    constexpr int STGB = (TBMT + TBN) * 128;
    constexpr int BOFF = TBMT * 128;
    constexpr int WM = TBMT / 4;          // 32 or 16
    constexpr int AMT = WM / 16;          // 2 or 1

    extern __shared__ char smraw[];
    int which = blockIdx.z;
    const __half* B   = which == 0 ? Bp0   : (which == 1 ? Bp1   : Bp2);
    const float* bias = which == 0 ? bias0 : (which == 1 ? bias1 : bias2);
    OT*          C    = which == 0 ? C0    : (which == 1 ? C1    : C2);

    int tid = threadIdx.x, warp = tid >> 5, lane = tid & 31;
    int bm = blockIdx.y * TBMT, bn = blockIdx.x * TBN;
    int wm = (warp >> 1) * WM;   // 4 warp-rows
    int wn = (warp & 1) * 64;    // 2 warp-cols

    float acc[AMT][8][4];
    #pragma unroll
    for (int i = 0; i < AMT; i++)
        #pragma unroll
        for (int j = 0; j < 8; j++)
            #pragma unroll
            for (int e = 0; e < 4; e++) acc[i][j][e] = 0.f;

    uint32_t smb = (uint32_t)__cvta_generic_to_shared(smraw);

    auto load_stage = [&](int slot, int k0) {
        uint32_t sb = smb + (uint32_t)slot * STGB;
        #pragma unroll
        for (int i = 0; i < (TBMT * 8) / 256; i++) {   // A rows x 8 granules
            int idx = tid + i * 256;
            int r = idx >> 3, g = idx & 7;
            cpasync16(sb + (uint32_t)(r * 128 + ((g ^ (r & 7)) << 4)),
                      A + (size_t)(bm + r) * K + k0 + g * 8);
        }
        #pragma unroll
        for (int i = 0; i < 4; i++) {                  // B: 128 rows x 8 granules
            int idx = tid + i * 256;
            int r = idx >> 3, g = idx & 7;
            cpasync16(sb + BOFF + (uint32_t)(r * 128 + ((g ^ (r & 7)) << 4)),
                      B + (size_t)(bn + r) * K + k0 + g * 8);
        }
    };

    auto compute_stage = [&](int s) {
        uint32_t base = smb + (uint32_t)s * STGB;
        #pragma unroll
        for (int ks = 0; ks < 4; ks++) {        // k16 steps within BK=64
            uint32_t a[AMT][4], b[4][4];
            #pragma unroll
            for (int mt = 0; mt < AMT; mt++) {
                int arow = wm + mt * 16 + (lane & 15);
                int gA = ks * 2 + (lane >> 4);
                ldsm4(a[mt], base + (uint32_t)(arow * 128 + ((gA ^ (arow & 7)) << 4)));
            }
            #pragma unroll
            for (int p = 0; p < 4; p++) {
                int brow = wn + p * 16 + ((lane >> 4) << 3) + (lane & 7);
                int gB = ks * 2 + ((lane >> 3) & 1);
                ldsm4(b[p], base + BOFF + (uint32_t)(brow * 128 + ((gB ^ (brow & 7)) << 4)));
            }
            #pragma unroll
            for (int p = 0; p < 4; p++) {
                #pragma unroll
                for (int mt = 0; mt < AMT; mt++) {
                    mma16(acc[mt][2 * p],     a[mt], b[p][0], b[p][1]);
                    mma16(acc[mt][2 * p + 1], a[mt], b[p][2], b[p][3]);
                }
            }
        }
    };

    int KT = K / TBK;
    load_stage(0, 0);
    asm volatile("cp.async.commit_group;");
    load_stage(1, TBK);
    asm volatile("cp.async.commit_group;");

    for (int kt = 0; kt < KT; kt++) {
        asm volatile("cp.async.wait_group 1;");
        __syncthreads();
        if (kt + 2 < KT) load_stage((kt + 2) % GSTAGES, (kt + 2) * TBK);
        asm volatile("cp.async.commit_group;");
        compute_stage(kt % GSTAGES);
    }

    #pragma unroll
    for (int mt = 0; mt < AMT; mt++) {
        int r0 = bm + wm + mt * 16 + (lane >> 2);
        #pragma unroll
        for (int nt = 0; nt < 8; nt++) {
            int cn = bn + wn + nt * 8 + (lane & 3) * 2;
            float b0 = bias[cn], b1 = bias[cn + 1];
            float v0 = acc[mt][nt][0] + b0;
            float v1 = acc[mt][nt][1] + b1;
            float v2 = acc[mt][nt][2] + b0;
            float v3 = acc[mt][nt][3] + b1;
            if (RESID) {
                v0 += R[(size_t)r0 * N + cn];
                v1 += R[(size_t)r0 * N + cn + 1];
                v2 += R[(size_t)(r0 + 8) * N + cn];
                v3 += R[(size_t)(r0 + 8) * N + cn + 1];
            }
            if (GELU) {
                v0 = 0.5f * v0 * (1.f + erff(v0 * 0.70710678118f));
                v1 = 0.5f * v1 * (1.f + erff(v1 * 0.70710678118f));
                v2 = 0.5f * v2 * (1.f + erff(v2 * 0.70710678118f));
                v3 = 0.5f * v3 * (1.f + erff(v3 * 0.70710678118f));
            }
            store2(C + (size_t)r0 * N + cn,       v0, v1);
            store2(C + (size_t)(r0 + 8) * N + cn, v2, v3);
        }
    }
}

#define GSMEM128 (GSTAGES * (128 + TBN) * 128)   // 98304
#define GSMEM64  (GSTAGES * (64 + TBN) * 128)    // 73728

// ---------------- fp16 flash attention (KV64 tiles, cp.async prefetch) -----
// grid (L/128, NH, B). 256 threads = 8 warps, each warp owns 16 q rows.
#define KVT 64
#define NKB (LSEQ / KVT)     // 32
#define FSTR 72              // halves per row (64 + 8 pad) = 144B
#define FA_SMEM ((128 * FSTR + 2 * KVT * FSTR + 2 * KVT * FSTR + 128 * FSTR) * 2 + 2 * KVT * 4)

__global__ void __launch_bounds__(256, 2) flash_kernel(
    const __half* __restrict__ Q, const __half* __restrict__ Kb,
    const __half* __restrict__ Vb, const unsigned char* __restrict__ msk,
    __half* __restrict__ O)
{
    extern __shared__ char fsm[];
    __half* Qs = (__half*)fsm;                 // [128][72]
    __half* Ks = Qs + 128 * FSTR;              // [2][64][72]
    __half* Vs = Ks + 2 * KVT * FSTR;          // [2][64][72]
    __half* Ps = Vs + 2 * KVT * FSTR;          // [128][72]
    float*  Mb = (float*)(Ps + 128 * FSTR);    // [2][64]
    uint32_t qs_b = (uint32_t)__cvta_generic_to_shared(Qs);
    uint32_t ks_b = (uint32_t)__cvta_generic_to_shared(Ks);
    uint32_t vs_b = (uint32_t)__cvta_generic_to_shared(Vs);
    uint32_t ps_b = (uint32_t)__cvta_generic_to_shared(Ps);

    int qb = blockIdx.x, h = blockIdx.y, b = blockIdx.z;
    int tid = threadIdx.x, warp = tid >> 5, lane = tid & 31;

    size_t base_q = ((size_t)(b * LSEQ + qb * 128)) * HID + h * HDIM;
    #pragma unroll
    for (int i = 0; i < 4; i++) {
        int idx = tid + i * 256;
        int r = idx >> 3, g = idx & 7;
        cpasync16(qs_b + (uint32_t)(r * 144 + g * 16),
                  Q + base_q + (size_t)r * HID + g * 8);
    }

    auto load_kv = [&](int kb, int buf) {
        size_t base_k = ((size_t)(b * LSEQ + kb * KVT)) * HID + h * HDIM;
        uint32_t boff = (uint32_t)(buf * KVT * 144);
        #pragma unroll
        for (int i = 0; i < 2; i++) {          // 64 rows x 8 granules = 512 each
            int idx = tid + i * 256;
            int r = idx >> 3, g = idx & 7;
            uint32_t so = (uint32_t)(r * 144 + g * 16);
            cpasync16(ks_b + boff + so, Kb + base_k + (size_t)r * HID + g * 8);
            cpasync16(vs_b + boff + so, Vb + base_k + (size_t)r * HID + g * 8);
        }
        if (tid < KVT)
            Mb[buf * KVT + tid] = msk[b * LSEQ + kb * KVT + tid] ? -1e30f : 0.f;
    };

    load_kv(0, 0);
    asm volatile("cp.async.commit_group;");

    float Oacc[8][4];
    #pragma unroll
    for (int i = 0; i < 8; i++)
        #pragma unroll
        for (int e = 0; e < 4; e++) Oacc[i][e] = 0.f;
    float mrow[2] = {-1e30f, -1e30f}, lrow[2] = {0.f, 0.f};

    for (int kb = 0; kb < NKB; kb++) {
        int cur = kb & 1;
        asm volatile("cp.async.wait_group 0;");
        __syncthreads();
        if (kb + 1 < NKB) {
            load_kv(kb + 1, cur ^ 1);
            asm volatile("cp.async.commit_group;");
        }
        uint32_t kbuf = ks_b + (uint32_t)(cur * KVT * 144);
        uint32_t vbuf = vs_b + (uint32_t)(cur * KVT * 144);
        const float* mb = Mb + cur * KVT;

        float sacc[8][4];
        #pragma unroll
        for (int i = 0; i < 8; i++)
            #pragma unroll
            for (int e = 0; e < 4; e++) sacc[i][e] = 0.f;

        #pragma unroll
        for (int ks = 0; ks < 4; ks++) {
            uint32_t af[4];
            int arow = warp * 16 + (lane & 15);
            ldsm4(af, qs_b + (uint32_t)(arow * 144 + ks * 32 + (lane >> 4) * 16));
            #pragma unroll
            for (int nt2 = 0; nt2 < 4; nt2++) {
                uint32_t bf[4];
                int brow = nt2 * 16 + ((lane >> 4) << 3) + (lane & 7);
                ldsm4(bf, kbuf + (uint32_t)(brow * 144 + ks * 32 + ((lane >> 3) & 1) * 16));
                mma16(sacc[nt2 * 2],     af, bf[0], bf[1]);
                mma16(sacc[nt2 * 2 + 1], af, bf[2], bf[3]);
            }
        }

        #pragma unroll
        for (int j = 0; j < 2; j++) {
            float tmax = -1e30f;
            #pragma unroll
            for (int nt = 0; nt < 8; nt++) {
                #pragma unroll
                for (int e = 0; e < 2; e++) {
                    int kc = nt * 8 + (lane & 3) * 2 + e;
                    float sv = sacc[nt][j * 2 + e] * 0.125f + mb[kc];
                    sacc[nt][j * 2 + e] = sv;
                    tmax = fmaxf(tmax, sv);
                }
            }
            tmax = fmaxf(tmax, __shfl_xor_sync(0xffffffffu, tmax, 1));
            tmax = fmaxf(tmax, __shfl_xor_sync(0xffffffffu, tmax, 2));
            float mnew  = fmaxf(mrow[j], tmax);
            float alpha = __expf(mrow[j] - mnew);
            mrow[j] = mnew;
            float psum = 0.f;
            int rl = warp * 16 + (lane >> 2) + j * 8;
            #pragma unroll
            for (int nt = 0; nt < 8; nt++) {
                float p0 = __expf(sacc[nt][j * 2]     - mnew);
                float p1 = __expf(sacc[nt][j * 2 + 1] - mnew);
                psum += p0 + p1;
                *(half2*)&Ps[rl * FSTR + nt * 8 + (lane & 3) * 2] =
                    __floats2half2_rn(p0, p1);
            }
            psum += __shfl_xor_sync(0xffffffffu, psum, 1);
            psum += __shfl_xor_sync(0xffffffffu, psum, 2);
            lrow[j] = lrow[j] * alpha + psum;
            #pragma unroll
            for (int nt = 0; nt < 8; nt++) {
                Oacc[nt][j * 2]     *= alpha;
                Oacc[nt][j * 2 + 1] *= alpha;
            }
        }

        #pragma unroll
        for (int ks = 0; ks < 4; ks++) {
            uint32_t af[4];
            int arow = warp * 16 + (lane & 15);
            ldsm4(af, ps_b + (uint32_t)(arow * 144 + ks * 32 + (lane >> 4) * 16));
            #pragma unroll
            for (int nt2 = 0; nt2 < 4; nt2++) {
                uint32_t bf[4];
                int vrow = ks * 16 + ((lane >> 3) & 1) * 8 + (lane & 7);
                ldsm4t(bf, vbuf + (uint32_t)(vrow * 144 + nt2 * 32 + (lane >> 4) * 16));
                mma16(Oacc[nt2 * 2],     af, bf[0], bf[1]);
                mma16(Oacc[nt2 * 2 + 1], af, bf[2], bf[3]);
            }
        }
    }

    #pragma unroll
    for (int j = 0; j < 2; j++) {
        float inv = 1.f / lrow[j];
        int row = qb * 128 + warp * 16 + (lane >> 2) + j * 8;
        size_t ob = ((size_t)(b * LSEQ + row)) * HID + h * HDIM;
        #pragma unroll
        for (int nt = 0; nt < 8; nt++) {
            int cc = nt * 8 + (lane & 3) * 2;
            *(half2*)&O[ob + cc] =
                __floats2half2_rn(Oacc[nt][j * 2] * inv, Oacc[nt][j * 2 + 1] * inv);
        }
    }
}

// ---------------- launch ----------------------------------------------------
extern "C" void kernel_launch(void* const* d_in, const int* in_sizes, int n_in,
                              void* d_out, int out_size)
{
    const float* x    = (const float*)d_in[0];
    const float* cond = (const float*)d_in[1];
    const unsigned char* kpm = (const unsigned char*)d_in[2];
    const float* w_ad1 = (const float*)d_in[3];
    const float* b_ad1 = (const float*)d_in[4];
    const float* w_ad2 = (const float*)d_in[5];
    const float* b_ad2 = (const float*)d_in[6];
    const float* wq = (const float*)d_in[7];
    const float* bq = (const float*)d_in[8];
    const float* wk = (const float*)d_in[9];
    const float* bk = (const float*)d_in[10];
    const float* wv = (const float*)d_in[11];
    const float* bv = (const float*)d_in[12];
    const float* wo = (const float*)d_in[13];
    const float* bo = (const float*)d_in[14];
    const float* w1 = (const float*)d_in[15];
    const float* b1 = (const float*)d_in[16];
    const float* w2 = (const float*)d_in[17];
    const float* b2 = (const float*)d_in[18];
    float* out = (float*)d_out;

    __half *p_normed, *p_q, *p_k, *p_v, *p_attn, *p_h;
    __half *p_rwq, *p_rwk, *p_rwv, *p_rwo, *p_rw1, *p_rw2;
    float *p_ss;
    cudaGetSymbolAddress((void**)&p_normed, g_normed);
    cudaGetSymbolAddress((void**)&p_q,    g_q);
    cudaGetSymbolAddress((void**)&p_k,    g_k);
    cudaGetSymbolAddress((void**)&p_v,    g_v);
    cudaGetSymbolAddress((void**)&p_attn, g_attn);
    cudaGetSymbolAddress((void**)&p_h,    g_h);
    cudaGetSymbolAddress((void**)&p_ss,   g_ss);
    cudaGetSymbolAddress((void**)&p_rwq,  g_rwq);
    cudaGetSymbolAddress((void**)&p_rwk,  g_rwk);
    cudaGetSymbolAddress((void**)&p_rwv,  g_rwv);
    cudaGetSymbolAddress((void**)&p_rwo,  g_rwo);
    cudaGetSymbolAddress((void**)&p_rw1,  g_rw1);
    cudaGetSymbolAddress((void**)&p_rw2,  g_rw2);

    cudaFuncSetAttribute(flash_kernel,
                         cudaFuncAttributeMaxDynamicSharedMemorySize, FA_SMEM);
    cudaFuncSetAttribute(gemm2<false, false, __half, 128>,
                         cudaFuncAttributeMaxDynamicSharedMemorySize, GSMEM128);
    cudaFuncSetAttribute(gemm2<true, false, __half, 128>,
                         cudaFuncAttributeMaxDynamicSharedMemorySize, GSMEM128);
    cudaFuncSetAttribute(gemm2<false, true, float, 64>,
                         cudaFuncAttributeMaxDynamicSharedMemorySize, GSMEM64);

    // 0. weight conversion + adaLN modulation (merged, independent work)
    prep_kernel<<<13312, 256>>>(wq, wk, wv, wo, w1, w2,
                                p_rwq, p_rwk, p_rwv, p_rwo, p_rw1, p_rw2,
                                cond, w_ad1, b_ad1, w_ad2, b_ad2, p_ss);
    // 1. normed1 = LN(x) * (1+scale1) + shift1  (fp16)
    adaln_kernel<<<MTOT, 256>>>(x, p_ss, p_normed);
    // 2. fused q, k, v projections (fp16 out) — 768 CTAs, 2/SM
    gemm2<false, false, __half, 128><<<dim3(HID / TBN, MTOT / 128, 3), 256, GSMEM128>>>(
        p_normed, p_rwq, p_rwk, p_rwv, bq, bk, bv, nullptr,
        p_q, p_k, p_v, MTOT, HID, HID);
    // 3. attention (fp16 in/out)
    flash_kernel<<<dim3(LSEQ / 128, NHEAD, BATCH), 256, FA_SMEM>>>(
        p_q, p_k, p_v, kpm, p_attn);
    // 4. x1 = x + attn @ wo^T + bo   (fp32, into d_out) — 512 fine CTAs
    gemm2<false, true, float, 64><<<dim3(HID / TBN, MTOT / 64, 1), 256, GSMEM64>>>(
        p_attn, p_rwo, p_rwo, p_rwo, bo, bo, bo, x,
        out, out, out, MTOT, HID, HID);
    // 5. normed2 = LN(x1) * (1+scale2) + shift2  (fp16)
    adaln_kernel<<<MTOT, 256>>>(out, p_ss + BATCH * 2048, p_normed);
    // 6. h = gelu(normed2 @ w1^T + b1)  (fp16 out) — 1024 CTAs, balanced
    gemm2<true, false, __half, 128><<<dim3(MLPD / TBN, MTOT / 128, 1), 256, GSMEM128>>>(
        p_normed, p_rw1, p_rw1, p_rw1, b1, b1, b1, nullptr,
        p_h, p_h, p_h, MTOT, MLPD, HID);
    // 7. out = x1 + h @ w2^T + b2   (fp32, in-place) — 512 fine CTAs vs 256:
    //    fixes the 108x2-vs-40x1 SM imbalance of the coarse grid
    gemm2<false, true, float, 64><<<dim3(HID / TBN, MTOT / 64, 1), 256, GSMEM64>>>(
        p_h, p_rw2, p_rw2, p_rw2, b2, b2, b2, out,
        out, out, out, MTOT, HID, MLPD);
}

// round 14
// speedup vs baseline: 1.0673x; 1.0673x over previous
#include <cuda_runtime.h>
#include <cuda_fp16.h>
#include <cstdint>
#include <cstdio>

#define HID   1024
#define CDIM  1024
#define NHEAD 16
#define HDIM  64
#define LSEQ  2048
#define BATCH 2
#define MTOT  4096   // B*L
#define MLPD  4096

// q pre-scale: 1/sqrt(64) * log2(e)  -> softmax runs in exp2 domain
#define QSCALE_F 0.180336879f

// ---------------- scratch (static device globals; no cudaMalloc allowed) ---
__device__ __half g_normed[MTOT * HID];
__device__ __half g_q[MTOT * HID];
__device__ __half g_k[MTOT * HID];
__device__ __half g_v[MTOT * HID];
__device__ __half g_attn[MTOT * HID];
__device__ __half g_h[MTOT * MLPD];
__device__ float  g_ss[2 * BATCH * 2048];   // [layer][batch][2H]
// fp16 pre-converted weights
__device__ __half g_rwq[HID * HID];
__device__ __half g_rwk[HID * HID];
__device__ __half g_rwv[HID * HID];
__device__ __half g_rwo[HID * HID];
__device__ __half g_rw1[MLPD * HID];
__device__ __half g_rw2[HID * MLPD];

// ---------------- helpers --------------------------------------------------
__device__ __forceinline__ void mma16(float* d, const uint32_t* a,
                                      uint32_t b0, uint32_t b1) {
    asm volatile(
        "mma.sync.aligned.m16n8k16.row.col.f32.f16.f16.f32 "
        "{%0,%1,%2,%3}, {%4,%5,%6,%7}, {%8,%9}, {%0,%1,%2,%3};\n"
        : "+f"(d[0]), "+f"(d[1]), "+f"(d[2]), "+f"(d[3])
        : "r"(a[0]), "r"(a[1]), "r"(a[2]), "r"(a[3]), "r"(b0), "r"(b1));
}

__device__ __forceinline__ void ldsm4(uint32_t* r, uint32_t addr) {
    asm volatile("ldmatrix.sync.aligned.m8n8.x4.shared.b16 {%0,%1,%2,%3}, [%4];"
        : "=r"(r[0]), "=r"(r[1]), "=r"(r[2]), "=r"(r[3]) : "r"(addr));
}

__device__ __forceinline__ void ldsm4t(uint32_t* r, uint32_t addr) {
    asm volatile("ldmatrix.sync.aligned.m8n8.x4.trans.shared.b16 {%0,%1,%2,%3}, [%4];"
        : "=r"(r[0]), "=r"(r[1]), "=r"(r[2]), "=r"(r[3]) : "r"(addr));
}

__device__ __forceinline__ void cpasync16(uint32_t dst, const void* src) {
    asm volatile("cp.async.cg.shared.global [%0], [%1], 16;" :: "r"(dst), "l"(src));
}

__device__ __forceinline__ float exp2a(float x) {
    float y;
    asm("ex2.approx.f32 %0, %1;" : "=f"(y) : "f"(x));
    return y;
}

__device__ __forceinline__ void store2(float* p, float a, float b) {
    *(float2*)p = make_float2(a, b);
}
__device__ __forceinline__ void store2(__half* p, float a, float b) {
    *(half2*)p = __floats2half2_rn(a, b);
}

// ---------------- fused prep: weight fp16 conversion + adaLN modulation ----
__global__ void __launch_bounds__(256) prep_kernel(
    const float* __restrict__ wq, const float* __restrict__ wk,
    const float* __restrict__ wv, const float* __restrict__ wo,
    const float* __restrict__ w1, const float* __restrict__ w2,
    __half* __restrict__ rq, __half* __restrict__ rk,
    __half* __restrict__ rv, __half* __restrict__ ro,
    __half* __restrict__ r1, __half* __restrict__ r2,
    const float* __restrict__ cond,
    const float* __restrict__ wa1, const float* __restrict__ ba1,
    const float* __restrict__ wa2, const float* __restrict__ ba2,
    float* __restrict__ ss)
{
    if (blockIdx.x < 12288) {
        const int S = 262144; // 1M floats in float4 units
        int idx = blockIdx.x * 256 + threadIdx.x;  // 0 .. 3145727
        const float* s; __half* d; int off;
        if      (idx <     S) { s = wq; d = rq; off = idx; }
        else if (idx < 2 * S) { s = wk; d = rk; off = idx - S; }
        else if (idx < 3 * S) { s = wv; d = rv; off = idx - 2 * S; }
        else if (idx < 4 * S) { s = wo; d = ro; off = idx - 3 * S; }
        else if (idx < 8 * S) { s = w1; d = r1; off = idx - 4 * S; }
        else                  { s = w2; d = r2; off = idx - 8 * S; }
        float4 v = ((const float4*)s)[off];
        half2 h01 = __floats2half2_rn(v.x, v.y);
        half2 h23 = __floats2half2_rn(v.z, v.w);
        ((half2*)d)[off * 2]     = h01;
        ((half2*)d)[off * 2 + 1] = h23;
    } else {
        int warp = threadIdx.x >> 5, lane = threadIdx.x & 31;
        int gw = (blockIdx.x - 12288) * 8 + warp;  // 0..8191
        int layer = gw >> 12;
        int rem = gw & 4095;
        int b = rem >> 11;
        int row = rem & 2047;
        const float* W  = layer ? wa2 : wa1;
        const float* bv = layer ? ba2 : ba1;
        const float* c  = cond + b * CDIM;
        const float* wr = W + (size_t)row * CDIM;
        float s = 0.f;
        for (int k = lane; k < CDIM; k += 32) s += c[k] * wr[k];
        #pragma unroll
        for (int o = 16; o > 0; o >>= 1) s += __shfl_xor_sync(0xffffffffu, s, o);
        if (lane == 0) ss[layer * (BATCH * 2048) + b * 2048 + row] = s + bv[row];
    }
}

// ---------------- LayerNorm * (1+scale) + shift (output fp16) --------------
__global__ void __launch_bounds__(256) adaln_kernel(
    const float* __restrict__ x, const float* __restrict__ ss,
    __half* __restrict__ out)
{
    int row = blockIdx.x;
    int b = row >> 11;
    const float* xr = x + (size_t)row * HID;
    float v[4];
    float s = 0.f, sq = 0.f;
    #pragma unroll
    for (int i = 0; i < 4; i++) {
        v[i] = xr[threadIdx.x + i * 256];
        s += v[i];
        sq += v[i] * v[i];
    }
    __shared__ float red[16];
    #pragma unroll
    for (int o = 16; o > 0; o >>= 1) {
        s  += __shfl_xor_sync(0xffffffffu, s,  o);
        sq += __shfl_xor_sync(0xffffffffu, sq, o);
    }
    int warp = threadIdx.x >> 5, lane = threadIdx.x & 31;
    if (lane == 0) { red[warp] = s; red[warp + 8] = sq; }
    __syncthreads();
    if (warp == 0) {
        float a  = lane < 8 ? red[lane] : 0.f;
        float c2 = lane < 8 ? red[lane + 8] : 0.f;
        #pragma unroll
        for (int o = 4; o > 0; o >>= 1) {
            a  += __shfl_xor_sync(0xffffffffu, a,  o);
            c2 += __shfl_xor_sync(0xffffffffu, c2, o);
        }
        if (lane == 0) { red[0] = a; red[1] = c2; }
    }
    __syncthreads();
    float mean = red[0] * (1.f / HID);
    float var  = red[1] * (1.f / HID) - mean * mean;
    float rs   = rsqrtf(var + 1e-5f);
    const float* sc = ss + b * 2048;
    #pragma unroll
    for (int i = 0; i < 4; i++) {
        int c = threadIdx.x + i * 256;
        out[(size_t)row * HID + c] =
            __float2half_rn((v[i] - mean) * rs * (1.f + sc[c]) + sc[1024 + c]);
    }
}

// ---------------- pipelined FP16 GEMM: C = A @ B^T + bias (+resid)(gelu) ---
// R12-proven config: BM=128, BN=128, BK=64, 256 threads = 8 warps as 4x2,
// warp tile 32x64, 3-stage ring = 98 KB -> 2 CTAs/SM.
// QSC: multiply output by QSCALE_F when which==0 (Q pre-scale for exp2 softmax).
#define TBM 128
#define TBN 128
#define TBK 64
#define GSTAGES 3
#define STG_BYTES ((TBM + TBN) * 128)        // 32768
#define B_OFF (TBM * 128)                    // 16384
#define GSMEM (GSTAGES * STG_BYTES)          // 98304

template <bool GELU, bool RESID, bool QSC, typename OT>
__global__ void __launch_bounds__(256, 2) gemm2(
    const __half* __restrict__ A,
    const __half* __restrict__ Bp0, const __half* __restrict__ Bp1, const __half* __restrict__ Bp2,
    const float* __restrict__ bias0, const float* __restrict__ bias1, const float* __restrict__ bias2,
    const float* __restrict__ R,
    OT* __restrict__ C0, OT* __restrict__ C1, OT* __restrict__ C2,
    int M, int N, int K)
{
    extern __shared__ char smraw[];
    int which = blockIdx.z;
    const __half* B   = which == 0 ? Bp0   : (which == 1 ? Bp1   : Bp2);
    const float* bias = which == 0 ? bias0 : (which == 1 ? bias1 : bias2);
    OT*          C    = which == 0 ? C0    : (which == 1 ? C1    : C2);
    float osc = (QSC && which == 0) ? QSCALE_F : 1.f;

    int tid = threadIdx.x, warp = tid >> 5, lane = tid & 31;
    int bm = blockIdx.y * TBM, bn = blockIdx.x * TBN;
    int wm = (warp >> 1) * 32;   // 4 warp-rows of 32
    int wn = (warp & 1) * 64;    // 2 warp-cols of 64

    float acc[2][8][4];
    #pragma unroll
    for (int i = 0; i < 2; i++)
        #pragma unroll
        for (int j = 0; j < 8; j++)
            #pragma unroll
            for (int e = 0; e < 4; e++) acc[i][j][e] = 0.f;

    uint32_t smb = (uint32_t)__cvta_generic_to_shared(smraw);

    auto load_stage = [&](int slot, int k0) {
        uint32_t sb = smb + (uint32_t)slot * STG_BYTES;
        #pragma unroll
        for (int i = 0; i < 4; i++) {
            int idx = tid + i * 256;
            int r = idx >> 3, g = idx & 7;
            cpasync16(sb + (uint32_t)(r * 128 + ((g ^ (r & 7)) << 4)),
                      A + (size_t)(bm + r) * K + k0 + g * 8);
        }
        #pragma unroll
        for (int i = 0; i < 4; i++) {
            int idx = tid + i * 256;
            int r = idx >> 3, g = idx & 7;
            cpasync16(sb + B_OFF + (uint32_t)(r * 128 + ((g ^ (r & 7)) << 4)),
                      B + (size_t)(bn + r) * K + k0 + g * 8);
        }
    };

    auto compute_stage = [&](int s) {
        uint32_t base = smb + (uint32_t)s * STG_BYTES;
        #pragma unroll
        for (int ks = 0; ks < 4; ks++) {
            uint32_t a[2][4], b[4][4];
            #pragma unroll
            for (int mt = 0; mt < 2; mt++) {
                int arow = wm + mt * 16 + (lane & 15);
                int gA = ks * 2 + (lane >> 4);
                ldsm4(a[mt], base + (uint32_t)(arow * 128 + ((gA ^ (arow & 7)) << 4)));
            }
            #pragma unroll
            for (int p = 0; p < 4; p++) {
                int brow = wn + p * 16 + ((lane >> 4) << 3) + (lane & 7);
                int gB = ks * 2 + ((lane >> 3) & 1);
                ldsm4(b[p], base + B_OFF + (uint32_t)(brow * 128 + ((gB ^ (brow & 7)) << 4)));
            }
            #pragma unroll
            for (int p = 0; p < 4; p++) {
                #pragma unroll
                for (int mt = 0; mt < 2; mt++) {
                    mma16(acc[mt][2 * p],     a[mt], b[p][0], b[p][1]);
                    mma16(acc[mt][2 * p + 1], a[mt], b[p][2], b[p][3]);
                }
            }
        }
    };

    int KT = K / TBK;
    load_stage(0, 0);
    asm volatile("cp.async.commit_group;");
    load_stage(1, TBK);
    asm volatile("cp.async.commit_group;");

    for (int kt = 0; kt < KT; kt++) {
        asm volatile("cp.async.wait_group 1;");
        __syncthreads();
        if (kt + 2 < KT) load_stage((kt + 2) % GSTAGES, (kt + 2) * TBK);
        asm volatile("cp.async.commit_group;");
        compute_stage(kt % GSTAGES);
    }

    #pragma unroll
    for (int mt = 0; mt < 2; mt++) {
        int r0 = bm + wm + mt * 16 + (lane >> 2);
        #pragma unroll
        for (int nt = 0; nt < 8; nt++) {
            int cn = bn + wn + nt * 8 + (lane & 3) * 2;
            float b0 = bias[cn], b1 = bias[cn + 1];
            float v0 = acc[mt][nt][0] + b0;
            float v1 = acc[mt][nt][1] + b1;
            float v2 = acc[mt][nt][2] + b0;
            float v3 = acc[mt][nt][3] + b1;
            if (RESID) {
                v0 += R[(size_t)r0 * N + cn];
                v1 += R[(size_t)r0 * N + cn + 1];
                v2 += R[(size_t)(r0 + 8) * N + cn];
                v3 += R[(size_t)(r0 + 8) * N + cn + 1];
            }
            if (GELU) {
                v0 = 0.5f * v0 * (1.f + erff(v0 * 0.70710678118f));
                v1 = 0.5f * v1 * (1.f + erff(v1 * 0.70710678118f));
                v2 = 0.5f * v2 * (1.f + erff(v2 * 0.70710678118f));
                v3 = 0.5f * v3 * (1.f + erff(v3 * 0.70710678118f));
            }
            if (QSC) { v0 *= osc; v1 *= osc; v2 *= osc; v3 *= osc; }
            store2(C + (size_t)r0 * N + cn,       v0, v1);
            store2(C + (size_t)(r0 + 8) * N + cn, v2, v3);
        }
    }
}

// ---------------- fp16 flash attention (exp2-domain softmax) ---------------
// Q pre-scaled by 0.125*log2(e) in the QKV epilogue -> S is in exp2 units.
// grid (L/128, NH, B). 256 threads = 8 warps, each warp owns 16 q rows.
#define KVT 64
#define NKB (LSEQ / KVT)     // 32
#define FSTR 72              // halves per row (64 + 8 pad) = 144B
#define FA_SMEM ((128 * FSTR + 2 * KVT * FSTR + 2 * KVT * FSTR + 128 * FSTR) * 2 + 2 * KVT * 4)

__global__ void __launch_bounds__(256, 2) flash_kernel(
    const __half* __restrict__ Q, const __half* __restrict__ Kb,
    const __half* __restrict__ Vb, const unsigned char* __restrict__ msk,
    __half* __restrict__ O)
{
    extern __shared__ char fsm[];
    __half* Qs = (__half*)fsm;                 // [128][72]
    __half* Ks = Qs + 128 * FSTR;              // [2][64][72]
    __half* Vs = Ks + 2 * KVT * FSTR;          // [2][64][72]
    __half* Ps = Vs + 2 * KVT * FSTR;          // [128][72]
    float*  Mb = (float*)(Ps + 128 * FSTR);    // [2][64]
    uint32_t qs_b = (uint32_t)__cvta_generic_to_shared(Qs);
    uint32_t ks_b = (uint32_t)__cvta_generic_to_shared(Ks);
    uint32_t vs_b = (uint32_t)__cvta_generic_to_shared(Vs);
    uint32_t ps_b = (uint32_t)__cvta_generic_to_shared(Ps);

    int qb = blockIdx.x, h = blockIdx.y, b = blockIdx.z;
    int tid = threadIdx.x, warp = tid >> 5, lane = tid & 31;

    size_t base_q = ((size_t)(b * LSEQ + qb * 128)) * HID + h * HDIM;
    #pragma unroll
    for (int i = 0; i < 4; i++) {
        int idx = tid + i * 256;
        int r = idx >> 3, g = idx & 7;
        cpasync16(qs_b + (uint32_t)(r * 144 + g * 16),
                  Q + base_q + (size_t)r * HID + g * 8);
    }

    auto load_kv = [&](int kb, int buf) {
        size_t base_k = ((size_t)(b * LSEQ + kb * KVT)) * HID + h * HDIM;
        uint32_t boff = (uint32_t)(buf * KVT * 144);
        #pragma unroll
        for (int i = 0; i < 2; i++) {
            int idx = tid + i * 256;
            int r = idx >> 3, g = idx & 7;
            uint32_t so = (uint32_t)(r * 144 + g * 16);
            cpasync16(ks_b + boff + so, Kb + base_k + (size_t)r * HID + g * 8);
            cpasync16(vs_b + boff + so, Vb + base_k + (size_t)r * HID + g * 8);
        }
        if (tid < KVT)
            Mb[buf * KVT + tid] = msk[b * LSEQ + kb * KVT + tid] ? -1e30f : 0.f;
    };

    load_kv(0, 0);
    asm volatile("cp.async.commit_group;");

    float Oacc[8][4];
    #pragma unroll
    for (int i = 0; i < 8; i++)
        #pragma unroll
        for (int e = 0; e < 4; e++) Oacc[i][e] = 0.f;
    float mrow[2] = {-1e30f, -1e30f}, lrow[2] = {0.f, 0.f};

    for (int kb = 0; kb < NKB; kb++) {
        int cur = kb & 1;
        asm volatile("cp.async.wait_group 0;");
        __syncthreads();
        if (kb + 1 < NKB) {
            load_kv(kb + 1, cur ^ 1);
            asm volatile("cp.async.commit_group;");
        }
        uint32_t kbuf = ks_b + (uint32_t)(cur * KVT * 144);
        uint32_t vbuf = vs_b + (uint32_t)(cur * KVT * 144);
        const float* mb = Mb + cur * KVT;

        // S = Q @ K^T  (exp2-domain; Q pre-scaled)
        float sacc[8][4];
        #pragma unroll
        for (int i = 0; i < 8; i++)
            #pragma unroll
            for (int e = 0; e < 4; e++) sacc[i][e] = 0.f;

        #pragma unroll
        for (int ks = 0; ks < 4; ks++) {
            uint32_t af[4];
            int arow = warp * 16 + (lane & 15);
            ldsm4(af, qs_b + (uint32_t)(arow * 144 + ks * 32 + (lane >> 4) * 16));
            #pragma unroll
            for (int nt2 = 0; nt2 < 4; nt2++) {
                uint32_t bf[4];
                int brow = nt2 * 16 + ((lane >> 4) << 3) + (lane & 7);
                ldsm4(bf, kbuf + (uint32_t)(brow * 144 + ks * 32 + ((lane >> 3) & 1) * 16));
                mma16(sacc[nt2 * 2],     af, bf[0], bf[1]);
                mma16(sacc[nt2 * 2 + 1], af, bf[2], bf[3]);
            }
        }

        // hoisted mask biases (shared across j)
        float2 mk[8];
        #pragma unroll
        for (int nt = 0; nt < 8; nt++)
            mk[nt] = *(const float2*)&mb[nt * 8 + (lane & 3) * 2];

        // online softmax per row (j=0: row r, j=1: row r+8), exp2 domain
        #pragma unroll
        for (int j = 0; j < 2; j++) {
            float tmax = -1e30f;
            #pragma unroll
            for (int nt = 0; nt < 8; nt++) {
                float s0 = sacc[nt][j * 2]     + mk[nt].x;
                float s1 = sacc[nt][j * 2 + 1] + mk[nt].y;
                sacc[nt][j * 2]     = s0;
                sacc[nt][j * 2 + 1] = s1;
                tmax = fmaxf(tmax, fmaxf(s0, s1));
            }
            tmax = fmaxf(tmax, __shfl_xor_sync(0xffffffffu, tmax, 1));
            tmax = fmaxf(tmax, __shfl_xor_sync(0xffffffffu, tmax, 2));
            float mnew  = fmaxf(mrow[j], tmax);
            float alpha = exp2a(mrow[j] - mnew);
            mrow[j] = mnew;
            float psum = 0.f;
            int rl = warp * 16 + (lane >> 2) + j * 8;
            #pragma unroll
            for (int nt = 0; nt < 8; nt++) {
                float p0 = exp2a(sacc[nt][j * 2]     - mnew);
                float p1 = exp2a(sacc[nt][j * 2 + 1] - mnew);
                psum += p0 + p1;
                *(half2*)&Ps[rl * FSTR + nt * 8 + (lane & 3) * 2] =
                    __floats2half2_rn(p0, p1);
            }
            psum += __shfl_xor_sync(0xffffffffu, psum, 1);
            psum += __shfl_xor_sync(0xffffffffu, psum, 2);
            lrow[j] = lrow[j] * alpha + psum;
            #pragma unroll
            for (int nt = 0; nt < 8; nt++) {
                Oacc[nt][j * 2]     *= alpha;
                Oacc[nt][j * 2 + 1] *= alpha;
            }
        }

        // O += P @ V  (Ps rows warp-private; no extra sync needed)
        #pragma unroll
        for (int ks = 0; ks < 4; ks++) {
            uint32_t af[4];
            int arow = warp * 16 + (lane & 15);
            ldsm4(af, ps_b + (uint32_t)(arow * 144 + ks * 32 + (lane >> 4) * 16));
            #pragma unroll
            for (int nt2 = 0; nt2 < 4; nt2++) {
                uint32_t bf[4];
                int vrow = ks * 16 + ((lane >> 3) & 1) * 8 + (lane & 7);
                ldsm4t(bf, vbuf + (uint32_t)(vrow * 144 + nt2 * 32 + (lane >> 4) * 16));
                mma16(Oacc[nt2 * 2],     af, bf[0], bf[1]);
                mma16(Oacc[nt2 * 2 + 1], af, bf[2], bf[3]);
            }
        }
    }

    #pragma unroll
    for (int j = 0; j < 2; j++) {
        float inv = 1.f / lrow[j];
        int row = qb * 128 + warp * 16 + (lane >> 2) + j * 8;
        size_t ob = ((size_t)(b * LSEQ + row)) * HID + h * HDIM;
        #pragma unroll
        for (int nt = 0; nt < 8; nt++) {
            int cc = nt * 8 + (lane & 3) * 2;
            *(half2*)&O[ob + cc] =
                __floats2half2_rn(Oacc[nt][j * 2] * inv, Oacc[nt][j * 2 + 1] * inv);
        }
    }
}

// ---------------- launch ----------------------------------------------------
extern "C" void kernel_launch(void* const* d_in, const int* in_sizes, int n_in,
                              void* d_out, int out_size)
{
    const float* x    = (const float*)d_in[0];
    const float* cond = (const float*)d_in[1];
    const unsigned char* kpm = (const unsigned char*)d_in[2];
    const float* w_ad1 = (const float*)d_in[3];
    const float* b_ad1 = (const float*)d_in[4];
    const float* w_ad2 = (const float*)d_in[5];
    const float* b_ad2 = (const float*)d_in[6];
    const float* wq = (const float*)d_in[7];
    const float* bq = (const float*)d_in[8];
    const float* wk = (const float*)d_in[9];
    const float* bk = (const float*)d_in[10];
    const float* wv = (const float*)d_in[11];
    const float* bv = (const float*)d_in[12];
    const float* wo = (const float*)d_in[13];
    const float* bo = (const float*)d_in[14];
    const float* w1 = (const float*)d_in[15];
    const float* b1 = (const float*)d_in[16];
    const float* w2 = (const float*)d_in[17];
    const float* b2 = (const float*)d_in[18];
    float* out = (float*)d_out;

    __half *p_normed, *p_q, *p_k, *p_v, *p_attn, *p_h;
    __half *p_rwq, *p_rwk, *p_rwv, *p_rwo, *p_rw1, *p_rw2;
    float *p_ss;
    cudaGetSymbolAddress((void**)&p_normed, g_normed);
    cudaGetSymbolAddress((void**)&p_q,    g_q);
    cudaGetSymbolAddress((void**)&p_k,    g_k);
    cudaGetSymbolAddress((void**)&p_v,    g_v);
    cudaGetSymbolAddress((void**)&p_attn, g_attn);
    cudaGetSymbolAddress((void**)&p_h,    g_h);
    cudaGetSymbolAddress((void**)&p_ss,   g_ss);
    cudaGetSymbolAddress((void**)&p_rwq,  g_rwq);
    cudaGetSymbolAddress((void**)&p_rwk,  g_rwk);
    cudaGetSymbolAddress((void**)&p_rwv,  g_rwv);
    cudaGetSymbolAddress((void**)&p_rwo,  g_rwo);
    cudaGetSymbolAddress((void**)&p_rw1,  g_rw1);
    cudaGetSymbolAddress((void**)&p_rw2,  g_rw2);

    cudaFuncSetAttribute(flash_kernel,
                         cudaFuncAttributeMaxDynamicSharedMemorySize, FA_SMEM);
    cudaFuncSetAttribute(gemm2<false, false, true, __half>,
                         cudaFuncAttributeMaxDynamicSharedMemorySize, GSMEM);
    cudaFuncSetAttribute(gemm2<false, true, false, float>,
                         cudaFuncAttributeMaxDynamicSharedMemorySize, GSMEM);
    cudaFuncSetAttribute(gemm2<true, false, false, __half>,
                         cudaFuncAttributeMaxDynamicSharedMemorySize, GSMEM);

    // 0. weight conversion + adaLN modulation (merged)
    prep_kernel<<<13312, 256>>>(wq, wk, wv, wo, w1, w2,
                                p_rwq, p_rwk, p_rwv, p_rwo, p_rw1, p_rw2,
                                cond, w_ad1, b_ad1, w_ad2, b_ad2, p_ss);
    // 1. normed1 = LN(x) * (1+scale1) + shift1  (fp16)
    adaln_kernel<<<MTOT, 256>>>(x, p_ss, p_normed);
    // 2. fused q, k, v projections (fp16 out; Q pre-scaled for exp2 softmax)
    gemm2<false, false, true, __half><<<dim3(HID / TBN, MTOT / TBM, 3), 256, GSMEM>>>(
        p_normed, p_rwq, p_rwk, p_rwv, bq, bk, bv, nullptr,
        p_q, p_k, p_v, MTOT, HID, HID);
    // 3. attention (fp16 in/out)
    flash_kernel<<<dim3(LSEQ / 128, NHEAD, BATCH), 256, FA_SMEM>>>(
        p_q, p_k, p_v, kpm, p_attn);
    // 4. x1 = x + attn @ wo^T + bo   (fp32, into d_out)
    gemm2<false, true, false, float><<<dim3(HID / TBN, MTOT / TBM, 1), 256, GSMEM>>>(
        p_attn, p_rwo, p_rwo, p_rwo, bo, bo, bo, x,
        out, out, out, MTOT, HID, HID);
    // 5. normed2 = LN(x1) * (1+scale2) + shift2  (fp16)
    adaln_kernel<<<MTOT, 256>>>(out, p_ss + BATCH * 2048, p_normed);
    // 6. h = gelu(normed2 @ w1^T + b1)  (fp16 out)
    gemm2<true, false, false, __half><<<dim3(MLPD / TBN, MTOT / TBM, 1), 256, GSMEM>>>(
        p_normed, p_rw1, p_rw1, p_rw1, b1, b1, b1, nullptr,
        p_h, p_h, p_h, MTOT, MLPD, HID);
    // 7. out = x1 + h @ w2^T + b2   (fp32, in-place on d_out)
    gemm2<false, true, false, float><<<dim3(HID / TBN, MTOT / TBM, 1), 256, GSMEM>>>(
        p_h, p_rw2, p_rw2, p_rw2, b2, b2, b2, out,
        out, out, out, MTOT, HID, MLPD);
}

// round 15
// speedup vs baseline: 1.0999x; 1.0305x over previous
#include <cuda_runtime.h>
#include <cuda_fp16.h>
#include <cstdint>
#include <cstdio>

#define HID   1024
#define CDIM  1024
#define NHEAD 16
#define HDIM  64
#define LSEQ  2048
#define BATCH 2
#define MTOT  4096   // B*L
#define MLPD  4096

// q pre-scale: 1/sqrt(64) * log2(e)  -> softmax runs in exp2 domain
#define QSCALE_F 0.180336879f

// ---------------- scratch (static device globals; no cudaMalloc allowed) ---
__device__ __half g_normed[MTOT * HID];
__device__ __half g_q[MTOT * HID];
__device__ __half g_k[MTOT * HID];
__device__ __half g_v[MTOT * HID];
__device__ __half g_attn[MTOT * HID];
__device__ __half g_h[MTOT * MLPD];
__device__ float  g_ss[2 * BATCH * 2048];   // [layer][batch][2H]
// fp16 pre-converted weights
__device__ __half g_rwq[HID * HID];
__device__ __half g_rwk[HID * HID];
__device__ __half g_rwv[HID * HID];
__device__ __half g_rwo[HID * HID];
__device__ __half g_rw1[MLPD * HID];
__device__ __half g_rw2[HID * MLPD];

// ---------------- helpers --------------------------------------------------
__device__ __forceinline__ void mma16(float* d, const uint32_t* a,
                                      uint32_t b0, uint32_t b1) {
    asm volatile(
        "mma.sync.aligned.m16n8k16.row.col.f32.f16.f16.f32 "
        "{%0,%1,%2,%3}, {%4,%5,%6,%7}, {%8,%9}, {%0,%1,%2,%3};\n"
        : "+f"(d[0]), "+f"(d[1]), "+f"(d[2]), "+f"(d[3])
        : "r"(a[0]), "r"(a[1]), "r"(a[2]), "r"(a[3]), "r"(b0), "r"(b1));
}

__device__ __forceinline__ void ldsm4(uint32_t* r, uint32_t addr) {
    asm volatile("ldmatrix.sync.aligned.m8n8.x4.shared.b16 {%0,%1,%2,%3}, [%4];"
        : "=r"(r[0]), "=r"(r[1]), "=r"(r[2]), "=r"(r[3]) : "r"(addr));
}

__device__ __forceinline__ void ldsm4t(uint32_t* r, uint32_t addr) {
    asm volatile("ldmatrix.sync.aligned.m8n8.x4.trans.shared.b16 {%0,%1,%2,%3}, [%4];"
        : "=r"(r[0]), "=r"(r[1]), "=r"(r[2]), "=r"(r[3]) : "r"(addr));
}

__device__ __forceinline__ void cpasync16(uint32_t dst, const void* src) {
    asm volatile("cp.async.cg.shared.global [%0], [%1], 16;" :: "r"(dst), "l"(src));
}

__device__ __forceinline__ float exp2a(float x) {
    float y;
    asm("ex2.approx.f32 %0, %1;" : "=f"(y) : "f"(x));
    return y;
}

__device__ __forceinline__ uint32_t packh2(float a, float b) {
    half2 h = __floats2half2_rn(a, b);
    return *(uint32_t*)&h;
}

__device__ __forceinline__ void store2(float* p, float a, float b) {
    *(float2*)p = make_float2(a, b);
}
__device__ __forceinline__ void store2(__half* p, float a, float b) {
    *(half2*)p = __floats2half2_rn(a, b);
}

// ---------------- fused prep: weight fp16 conversion + adaLN modulation ----
__global__ void __launch_bounds__(256) prep_kernel(
    const float* __restrict__ wq, const float* __restrict__ wk,
    const float* __restrict__ wv, const float* __restrict__ wo,
    const float* __restrict__ w1, const float* __restrict__ w2,
    __half* __restrict__ rq, __half* __restrict__ rk,
    __half* __restrict__ rv, __half* __restrict__ ro,
    __half* __restrict__ r1, __half* __restrict__ r2,
    const float* __restrict__ cond,
    const float* __restrict__ wa1, const float* __restrict__ ba1,
    const float* __restrict__ wa2, const float* __restrict__ ba2,
    float* __restrict__ ss)
{
    if (blockIdx.x < 12288) {
        const int S = 262144; // 1M floats in float4 units
        int idx = blockIdx.x * 256 + threadIdx.x;  // 0 .. 3145727
        const float* s; __half* d; int off;
        if      (idx <     S) { s = wq; d = rq; off = idx; }
        else if (idx < 2 * S) { s = wk; d = rk; off = idx - S; }
        else if (idx < 3 * S) { s = wv; d = rv; off = idx - 2 * S; }
        else if (idx < 4 * S) { s = wo; d = ro; off = idx - 3 * S; }
        else if (idx < 8 * S) { s = w1; d = r1; off = idx - 4 * S; }
        else                  { s = w2; d = r2; off = idx - 8 * S; }
        float4 v = ((const float4*)s)[off];
        half2 h01 = __floats2half2_rn(v.x, v.y);
        half2 h23 = __floats2half2_rn(v.z, v.w);
        ((half2*)d)[off * 2]     = h01;
        ((half2*)d)[off * 2 + 1] = h23;
    } else {
        int warp = threadIdx.x >> 5, lane = threadIdx.x & 31;
        int gw = (blockIdx.x - 12288) * 8 + warp;  // 0..8191
        int layer = gw >> 12;
        int rem = gw & 4095;
        int b = rem >> 11;
        int row = rem & 2047;
        const float* W  = layer ? wa2 : wa1;
        const float* bv = layer ? ba2 : ba1;
        const float* c  = cond + b * CDIM;
        const float* wr = W + (size_t)row * CDIM;
        float s = 0.f;
        for (int k = lane; k < CDIM; k += 32) s += c[k] * wr[k];
        #pragma unroll
        for (int o = 16; o > 0; o >>= 1) s += __shfl_xor_sync(0xffffffffu, s, o);
        if (lane == 0) ss[layer * (BATCH * 2048) + b * 2048 + row] = s + bv[row];
    }
}

// ---------------- LayerNorm * (1+scale) + shift (output fp16) --------------
__global__ void __launch_bounds__(256) adaln_kernel(
    const float* __restrict__ x, const float* __restrict__ ss,
    __half* __restrict__ out)
{
    int row = blockIdx.x;
    int b = row >> 11;
    const float* xr = x + (size_t)row * HID;
    float v[4];
    float s = 0.f, sq = 0.f;
    #pragma unroll
    for (int i = 0; i < 4; i++) {
        v[i] = xr[threadIdx.x + i * 256];
        s += v[i];
        sq += v[i] * v[i];
    }
    __shared__ float red[16];
    #pragma unroll
    for (int o = 16; o > 0; o >>= 1) {
        s  += __shfl_xor_sync(0xffffffffu, s,  o);
        sq += __shfl_xor_sync(0xffffffffu, sq, o);
    }
    int warp = threadIdx.x >> 5, lane = threadIdx.x & 31;
    if (lane == 0) { red[warp] = s; red[warp + 8] = sq; }
    __syncthreads();
    if (warp == 0) {
        float a  = lane < 8 ? red[lane] : 0.f;
        float c2 = lane < 8 ? red[lane + 8] : 0.f;
        #pragma unroll
        for (int o = 4; o > 0; o >>= 1) {
            a  += __shfl_xor_sync(0xffffffffu, a,  o);
            c2 += __shfl_xor_sync(0xffffffffu, c2, o);
        }
        if (lane == 0) { red[0] = a; red[1] = c2; }
    }
    __syncthreads();
    float mean = red[0] * (1.f / HID);
    float var  = red[1] * (1.f / HID) - mean * mean;
    float rs   = rsqrtf(var + 1e-5f);
    const float* sc = ss + b * 2048;
    #pragma unroll
    for (int i = 0; i < 4; i++) {
        int c = threadIdx.x + i * 256;
        out[(size_t)row * HID + c] =
            __float2half_rn((v[i] - mean) * rs * (1.f + sc[c]) + sc[1024 + c]);
    }
}

// ---------------- pipelined FP16 GEMM: C = A @ B^T + bias (+resid)(gelu) ---
// R12-proven config: BM=128, BN=128, BK=64, 256 threads = 8 warps as 4x2,
// warp tile 32x64, 3-stage ring = 98 KB -> 2 CTAs/SM.
// QSC: multiply output by QSCALE_F when which==0 (Q pre-scale for exp2 softmax).
#define TBM 128
#define TBN 128
#define TBK 64
#define GSTAGES 3
#define STG_BYTES ((TBM + TBN) * 128)        // 32768
#define B_OFF (TBM * 128)                    // 16384
#define GSMEM (GSTAGES * STG_BYTES)          // 98304

template <bool GELU, bool RESID, bool QSC, typename OT>
__global__ void __launch_bounds__(256, 2) gemm2(
    const __half* __restrict__ A,
    const __half* __restrict__ Bp0, const __half* __restrict__ Bp1, const __half* __restrict__ Bp2,
    const float* __restrict__ bias0, const float* __restrict__ bias1, const float* __restrict__ bias2,
    const float* __restrict__ R,
    OT* __restrict__ C0, OT* __restrict__ C1, OT* __restrict__ C2,
    int M, int N, int K)
{
    extern __shared__ char smraw[];
    int which = blockIdx.z;
    const __half* B   = which == 0 ? Bp0   : (which == 1 ? Bp1   : Bp2);
    const float* bias = which == 0 ? bias0 : (which == 1 ? bias1 : bias2);
    OT*          C    = which == 0 ? C0    : (which == 1 ? C1    : C2);
    float osc = (QSC && which == 0) ? QSCALE_F : 1.f;

    int tid = threadIdx.x, warp = tid >> 5, lane = tid & 31;
    int bm = blockIdx.y * TBM, bn = blockIdx.x * TBN;
    int wm = (warp >> 1) * 32;   // 4 warp-rows of 32
    int wn = (warp & 1) * 64;    // 2 warp-cols of 64

    float acc[2][8][4];
    #pragma unroll
    for (int i = 0; i < 2; i++)
        #pragma unroll
        for (int j = 0; j < 8; j++)
            #pragma unroll
            for (int e = 0; e < 4; e++) acc[i][j][e] = 0.f;

    uint32_t smb = (uint32_t)__cvta_generic_to_shared(smraw);

    auto load_stage = [&](int slot, int k0) {
        uint32_t sb = smb + (uint32_t)slot * STG_BYTES;
        #pragma unroll
        for (int i = 0; i < 4; i++) {
            int idx = tid + i * 256;
            int r = idx >> 3, g = idx & 7;
            cpasync16(sb + (uint32_t)(r * 128 + ((g ^ (r & 7)) << 4)),
                      A + (size_t)(bm + r) * K + k0 + g * 8);
        }
        #pragma unroll
        for (int i = 0; i < 4; i++) {
            int idx = tid + i * 256;
            int r = idx >> 3, g = idx & 7;
            cpasync16(sb + B_OFF + (uint32_t)(r * 128 + ((g ^ (r & 7)) << 4)),
                      B + (size_t)(bn + r) * K + k0 + g * 8);
        }
    };

    auto compute_stage = [&](int s) {
        uint32_t base = smb + (uint32_t)s * STG_BYTES;
        #pragma unroll
        for (int ks = 0; ks < 4; ks++) {
            uint32_t a[2][4], b[4][4];
            #pragma unroll
            for (int mt = 0; mt < 2; mt++) {
                int arow = wm + mt * 16 + (lane & 15);
                int gA = ks * 2 + (lane >> 4);
                ldsm4(a[mt], base + (uint32_t)(arow * 128 + ((gA ^ (arow & 7)) << 4)));
            }
            #pragma unroll
            for (int p = 0; p < 4; p++) {
                int brow = wn + p * 16 + ((lane >> 4) << 3) + (lane & 7);
                int gB = ks * 2 + ((lane >> 3) & 1);
                ldsm4(b[p], base + B_OFF + (uint32_t)(brow * 128 + ((gB ^ (brow & 7)) << 4)));
            }
            #pragma unroll
            for (int p = 0; p < 4; p++) {
                #pragma unroll
                for (int mt = 0; mt < 2; mt++) {
                    mma16(acc[mt][2 * p],     a[mt], b[p][0], b[p][1]);
                    mma16(acc[mt][2 * p + 1], a[mt], b[p][2], b[p][3]);
                }
            }
        }
    };

    int KT = K / TBK;
    load_stage(0, 0);
    asm volatile("cp.async.commit_group;");
    load_stage(1, TBK);
    asm volatile("cp.async.commit_group;");

    for (int kt = 0; kt < KT; kt++) {
        asm volatile("cp.async.wait_group 1;");
        __syncthreads();
        if (kt + 2 < KT) load_stage((kt + 2) % GSTAGES, (kt + 2) * TBK);
        asm volatile("cp.async.commit_group;");
        compute_stage(kt % GSTAGES);
    }

    #pragma unroll
    for (int mt = 0; mt < 2; mt++) {
        int r0 = bm + wm + mt * 16 + (lane >> 2);
        #pragma unroll
        for (int nt = 0; nt < 8; nt++) {
            int cn = bn + wn + nt * 8 + (lane & 3) * 2;
            float b0 = bias[cn], b1 = bias[cn + 1];
            float v0 = acc[mt][nt][0] + b0;
            float v1 = acc[mt][nt][1] + b1;
            float v2 = acc[mt][nt][2] + b0;
            float v3 = acc[mt][nt][3] + b1;
            if (RESID) {
                v0 += R[(size_t)r0 * N + cn];
                v1 += R[(size_t)r0 * N + cn + 1];
                v2 += R[(size_t)(r0 + 8) * N + cn];
                v3 += R[(size_t)(r0 + 8) * N + cn + 1];
            }
            if (GELU) {
                v0 = 0.5f * v0 * (1.f + erff(v0 * 0.70710678118f));
                v1 = 0.5f * v1 * (1.f + erff(v1 * 0.70710678118f));
                v2 = 0.5f * v2 * (1.f + erff(v2 * 0.70710678118f));
                v3 = 0.5f * v3 * (1.f + erff(v3 * 0.70710678118f));
            }
            if (QSC) { v0 *= osc; v1 *= osc; v2 *= osc; v3 *= osc; }
            store2(C + (size_t)r0 * N + cn,       v0, v1);
            store2(C + (size_t)(r0 + 8) * N + cn, v2, v3);
        }
    }
}

// ---------------- fp16 flash attention (exp2 softmax, register-resident P) -
// Q pre-scaled by 0.125*log2(e) in the QKV epilogue -> S is in exp2 units.
// P never touches smem: the S-accumulator lane layout IS the PV A-fragment
// layout (sacc[2t],sacc[2t+1] -> A-frag of K-chunk t), so exp2'd scores are
// packed straight into half2 MMA fragments.
// grid (L/128, NH, B). 256 threads = 8 warps, each warp owns 16 q rows.
#define KVT 64
#define NKB (LSEQ / KVT)     // 32
#define FSTR 72              // halves per row (64 + 8 pad) = 144B
#define FA_SMEM ((128 * FSTR + 2 * KVT * FSTR + 2 * KVT * FSTR) * 2 + 2 * KVT * 4)

__global__ void __launch_bounds__(256, 2) flash_kernel(
    const __half* __restrict__ Q, const __half* __restrict__ Kb,
    const __half* __restrict__ Vb, const unsigned char* __restrict__ msk,
    __half* __restrict__ O)
{
    extern __shared__ char fsm[];
    __half* Qs = (__half*)fsm;                 // [128][72]
    __half* Ks = Qs + 128 * FSTR;              // [2][64][72]
    __half* Vs = Ks + 2 * KVT * FSTR;          // [2][64][72]
    float*  Mb = (float*)(Vs + 2 * KVT * FSTR);// [2][64]
    uint32_t qs_b = (uint32_t)__cvta_generic_to_shared(Qs);
    uint32_t ks_b = (uint32_t)__cvta_generic_to_shared(Ks);
    uint32_t vs_b = (uint32_t)__cvta_generic_to_shared(Vs);

    int qb = blockIdx.x, h = blockIdx.y, b = blockIdx.z;
    int tid = threadIdx.x, warp = tid >> 5, lane = tid & 31;

    size_t base_q = ((size_t)(b * LSEQ + qb * 128)) * HID + h * HDIM;
    #pragma unroll
    for (int i = 0; i < 4; i++) {
        int idx = tid + i * 256;
        int r = idx >> 3, g = idx & 7;
        cpasync16(qs_b + (uint32_t)(r * 144 + g * 16),
                  Q + base_q + (size_t)r * HID + g * 8);
    }

    auto load_kv = [&](int kb, int buf) {
        size_t base_k = ((size_t)(b * LSEQ + kb * KVT)) * HID + h * HDIM;
        uint32_t boff = (uint32_t)(buf * KVT * 144);
        #pragma unroll
        for (int i = 0; i < 2; i++) {
            int idx = tid + i * 256;
            int r = idx >> 3, g = idx & 7;
            uint32_t so = (uint32_t)(r * 144 + g * 16);
            cpasync16(ks_b + boff + so, Kb + base_k + (size_t)r * HID + g * 8);
            cpasync16(vs_b + boff + so, Vb + base_k + (size_t)r * HID + g * 8);
        }
        if (tid < KVT)
            Mb[buf * KVT + tid] = msk[b * LSEQ + kb * KVT + tid] ? -1e30f : 0.f;
    };

    load_kv(0, 0);
    asm volatile("cp.async.commit_group;");

    float Oacc[8][4];
    #pragma unroll
    for (int i = 0; i < 8; i++)
        #pragma unroll
        for (int e = 0; e < 4; e++) Oacc[i][e] = 0.f;
    float m0 = -1e30f, m1 = -1e30f, l0 = 0.f, l1 = 0.f;

    for (int kb = 0; kb < NKB; kb++) {
        int cur = kb & 1;
        asm volatile("cp.async.wait_group 0;");
        __syncthreads();
        if (kb + 1 < NKB) {
            load_kv(kb + 1, cur ^ 1);
            asm volatile("cp.async.commit_group;");
        }
        uint32_t kbuf = ks_b + (uint32_t)(cur * KVT * 144);
        uint32_t vbuf = vs_b + (uint32_t)(cur * KVT * 144);
        const float* mb = Mb + cur * KVT;

        // S = Q @ K^T  (exp2-domain; Q pre-scaled)
        float sacc[8][4];
        #pragma unroll
        for (int i = 0; i < 8; i++)
            #pragma unroll
            for (int e = 0; e < 4; e++) sacc[i][e] = 0.f;

        #pragma unroll
        for (int ks = 0; ks < 4; ks++) {
            uint32_t af[4];
            int arow = warp * 16 + (lane & 15);
            ldsm4(af, qs_b + (uint32_t)(arow * 144 + ks * 32 + (lane >> 4) * 16));
            #pragma unroll
            for (int nt2 = 0; nt2 < 4; nt2++) {
                uint32_t bf[4];
                int brow = nt2 * 16 + ((lane >> 4) << 3) + (lane & 7);
                ldsm4(bf, kbuf + (uint32_t)(brow * 144 + ks * 32 + ((lane >> 3) & 1) * 16));
                mma16(sacc[nt2 * 2],     af, bf[0], bf[1]);
                mma16(sacc[nt2 * 2 + 1], af, bf[2], bf[3]);
            }
        }

        // mask + both-row max in one pass
        float2 mk[8];
        #pragma unroll
        for (int nt = 0; nt < 8; nt++)
            mk[nt] = *(const float2*)&mb[nt * 8 + (lane & 3) * 2];

        float t0 = -1e30f, t1 = -1e30f;
        #pragma unroll
        for (int nt = 0; nt < 8; nt++) {
            float s0 = sacc[nt][0] + mk[nt].x;
            float s1 = sacc[nt][1] + mk[nt].y;
            float s2 = sacc[nt][2] + mk[nt].x;
            float s3 = sacc[nt][3] + mk[nt].y;
            sacc[nt][0] = s0; sacc[nt][1] = s1;
            sacc[nt][2] = s2; sacc[nt][3] = s3;
            t0 = fmaxf(t0, fmaxf(s0, s1));
            t1 = fmaxf(t1, fmaxf(s2, s3));
        }
        t0 = fmaxf(t0, __shfl_xor_sync(0xffffffffu, t0, 1));
        t0 = fmaxf(t0, __shfl_xor_sync(0xffffffffu, t0, 2));
        t1 = fmaxf(t1, __shfl_xor_sync(0xffffffffu, t1, 1));
        t1 = fmaxf(t1, __shfl_xor_sync(0xffffffffu, t1, 2));
        float mn0 = fmaxf(m0, t0), mn1 = fmaxf(m1, t1);
        float al0 = exp2a(m0 - mn0), al1 = exp2a(m1 - mn1);
        m0 = mn0; m1 = mn1;

        // exp2 -> pack P directly into PV A-fragments (registers)
        uint32_t pa[4][4];
        float ps0 = 0.f, ps1 = 0.f;
        #pragma unroll
        for (int t = 0; t < 4; t++) {
            float p0 = exp2a(sacc[2 * t][0] - m0);
            float p1 = exp2a(sacc[2 * t][1] - m0);
            float p2 = exp2a(sacc[2 * t][2] - m1);
            float p3 = exp2a(sacc[2 * t][3] - m1);
            float p4 = exp2a(sacc[2 * t + 1][0] - m0);
            float p5 = exp2a(sacc[2 * t + 1][1] - m0);
            float p6 = exp2a(sacc[2 * t + 1][2] - m1);
            float p7 = exp2a(sacc[2 * t + 1][3] - m1);
            ps0 += (p0 + p1) + (p4 + p5);
            ps1 += (p2 + p3) + (p6 + p7);
            pa[t][0] = packh2(p0, p1);
            pa[t][1] = packh2(p2, p3);
            pa[t][2] = packh2(p4, p5);
            pa[t][3] = packh2(p6, p7);
        }
        ps0 += __shfl_xor_sync(0xffffffffu, ps0, 1);
        ps0 += __shfl_xor_sync(0xffffffffu, ps0, 2);
        ps1 += __shfl_xor_sync(0xffffffffu, ps1, 1);
        ps1 += __shfl_xor_sync(0xffffffffu, ps1, 2);
        l0 = l0 * al0 + ps0;
        l1 = l1 * al1 + ps1;
        #pragma unroll
        for (int nt = 0; nt < 8; nt++) {
            Oacc[nt][0] *= al0; Oacc[nt][1] *= al0;
            Oacc[nt][2] *= al1; Oacc[nt][3] *= al1;
        }

        // O += P @ V  (P in registers; V via ldmatrix.trans)
        #pragma unroll
        for (int ks = 0; ks < 4; ks++) {
            #pragma unroll
            for (int nt2 = 0; nt2 < 4; nt2++) {
                uint32_t bf[4];
                int vrow = ks * 16 + ((lane >> 3) & 1) * 8 + (lane & 7);
                ldsm4t(bf, vbuf + (uint32_t)(vrow * 144 + nt2 * 32 + (lane >> 4) * 16));
                mma16(Oacc[nt2 * 2],     pa[ks], bf[0], bf[1]);
                mma16(Oacc[nt2 * 2 + 1], pa[ks], bf[2], bf[3]);
            }
        }
    }

    {
        float inv0 = 1.f / l0, inv1 = 1.f / l1;
        int row = qb * 128 + warp * 16 + (lane >> 2);
        size_t ob0 = ((size_t)(b * LSEQ + row)) * HID + h * HDIM;
        size_t ob1 = ((size_t)(b * LSEQ + row + 8)) * HID + h * HDIM;
        #pragma unroll
        for (int nt = 0; nt < 8; nt++) {
            int cc = nt * 8 + (lane & 3) * 2;
            *(half2*)&O[ob0 + cc] =
                __floats2half2_rn(Oacc[nt][0] * inv0, Oacc[nt][1] * inv0);
            *(half2*)&O[ob1 + cc] =
                __floats2half2_rn(Oacc[nt][2] * inv1, Oacc[nt][3] * inv1);
        }
    }
}

// ---------------- launch ----------------------------------------------------
extern "C" void kernel_launch(void* const* d_in, const int* in_sizes, int n_in,
                              void* d_out, int out_size)
{
    const float* x    = (const float*)d_in[0];
    const float* cond = (const float*)d_in[1];
    const unsigned char* kpm = (const unsigned char*)d_in[2];
    const float* w_ad1 = (const float*)d_in[3];
    const float* b_ad1 = (const float*)d_in[4];
    const float* w_ad2 = (const float*)d_in[5];
    const float* b_ad2 = (const float*)d_in[6];
    const float* wq = (const float*)d_in[7];
    const float* bq = (const float*)d_in[8];
    const float* wk = (const float*)d_in[9];
    const float* bk = (const float*)d_in[10];
    const float* wv = (const float*)d_in[11];
    const float* bv = (const float*)d_in[12];
    const float* wo = (const float*)d_in[13];
    const float* bo = (const float*)d_in[14];
    const float* w1 = (const float*)d_in[15];
    const float* b1 = (const float*)d_in[16];
    const float* w2 = (const float*)d_in[17];
    const float* b2 = (const float*)d_in[18];
    float* out = (float*)d_out;

    __half *p_normed, *p_q, *p_k, *p_v, *p_attn, *p_h;
    __half *p_rwq, *p_rwk, *p_rwv, *p_rwo, *p_rw1, *p_rw2;
    float *p_ss;
    cudaGetSymbolAddress((void**)&p_normed, g_normed);
    cudaGetSymbolAddress((void**)&p_q,    g_q);
    cudaGetSymbolAddress((void**)&p_k,    g_k);
    cudaGetSymbolAddress((void**)&p_v,    g_v);
    cudaGetSymbolAddress((void**)&p_attn, g_attn);
    cudaGetSymbolAddress((void**)&p_h,    g_h);
    cudaGetSymbolAddress((void**)&p_ss,   g_ss);
    cudaGetSymbolAddress((void**)&p_rwq,  g_rwq);
    cudaGetSymbolAddress((void**)&p_rwk,  g_rwk);
    cudaGetSymbolAddress((void**)&p_rwv,  g_rwv);
    cudaGetSymbolAddress((void**)&p_rwo,  g_rwo);
    cudaGetSymbolAddress((void**)&p_rw1,  g_rw1);
    cudaGetSymbolAddress((void**)&p_rw2,  g_rw2);

    cudaFuncSetAttribute(flash_kernel,
                         cudaFuncAttributeMaxDynamicSharedMemorySize, FA_SMEM);
    cudaFuncSetAttribute(gemm2<false, false, true, __half>,
                         cudaFuncAttributeMaxDynamicSharedMemorySize, GSMEM);
    cudaFuncSetAttribute(gemm2<false, true, false, float>,
                         cudaFuncAttributeMaxDynamicSharedMemorySize, GSMEM);
    cudaFuncSetAttribute(gemm2<true, false, false, __half>,
                         cudaFuncAttributeMaxDynamicSharedMemorySize, GSMEM);

    // 0. weight conversion + adaLN modulation (merged)
    prep_kernel<<<13312, 256>>>(wq, wk, wv, wo, w1, w2,
                                p_rwq, p_rwk, p_rwv, p_rwo, p_rw1, p_rw2,
                                cond, w_ad1, b_ad1, w_ad2, b_ad2, p_ss);
    // 1. normed1 = LN(x) * (1+scale1) + shift1  (fp16)
    adaln_kernel<<<MTOT, 256>>>(x, p_ss, p_normed);
    // 2. fused q, k, v projections (fp16 out; Q pre-scaled for exp2 softmax)
    gemm2<false, false, true, __half><<<dim3(HID / TBN, MTOT / TBM, 3), 256, GSMEM>>>(
        p_normed, p_rwq, p_rwk, p_rwv, bq, bk, bv, nullptr,
        p_q, p_k, p_v, MTOT, HID, HID);
    // 3. attention (fp16 in/out; register-resident P)
    flash_kernel<<<dim3(LSEQ / 128, NHEAD, BATCH), 256, FA_SMEM>>>(
        p_q, p_k, p_v, kpm, p_attn);
    // 4. x1 = x + attn @ wo^T + bo   (fp32, into d_out)
    gemm2<false, true, false, float><<<dim3(HID / TBN, MTOT / TBM, 1), 256, GSMEM>>>(
        p_attn, p_rwo, p_rwo, p_rwo, bo, bo, bo, x,
        out, out, out, MTOT, HID, HID);
    // 5. normed2 = LN(x1) * (1+scale2) + shift2  (fp16)
    adaln_kernel<<<MTOT, 256>>>(out, p_ss + BATCH * 2048, p_normed);
    // 6. h = gelu(normed2 @ w1^T + b1)  (fp16 out)
    gemm2<true, false, false, __half><<<dim3(MLPD / TBN, MTOT / TBM, 1), 256, GSMEM>>>(
        p_normed, p_rw1, p_rw1, p_rw1, b1, b1, b1, nullptr,
        p_h, p_h, p_h, MTOT, MLPD, HID);
    // 7. out = x1 + h @ w2^T + b2   (fp32, in-place on d_out)
    gemm2<false, true, false, float><<<dim3(HID / TBN, MTOT / TBM, 1), 256, GSMEM>>>(
        p_h, p_rw2, p_rw2, p_rw2, b2, b2, b2, out,
        out, out, out, MTOT, HID, MLPD);
}

// round 16
// speedup vs baseline: 1.1101x; 1.0093x over previous
#include <cuda_runtime.h>
#include <cuda_fp16.h>
#include <cstdint>
#include <cstdio>

#define HID   1024
#define CDIM  1024
#define NHEAD 16
#define HDIM  64
#define LSEQ  2048
#define BATCH 2
#define MTOT  4096   // B*L
#define MLPD  4096

// q pre-scale: 1/sqrt(64) * log2(e)  -> softmax runs in exp2 domain
#define QSCALE_F 0.180336879f

// ---------------- scratch (static device globals; no cudaMalloc allowed) ---
__device__ __half g_normed[MTOT * HID];
__device__ __half g_q[MTOT * HID];
__device__ __half g_k[MTOT * HID];
__device__ __half g_v[MTOT * HID];
__device__ __half g_attn[MTOT * HID];
__device__ __half g_h[MTOT * MLPD];
__device__ float  g_ss[2 * BATCH * 2048];   // [layer][batch][2H]
// fp16 pre-converted weights
__device__ __half g_rwq[HID * HID];
__device__ __half g_rwk[HID * HID];
__device__ __half g_rwv[HID * HID];
__device__ __half g_rwo[HID * HID];
__device__ __half g_rw1[MLPD * HID];
__device__ __half g_rw2[HID * MLPD];

// ---------------- helpers --------------------------------------------------
__device__ __forceinline__ void mma16(float* d, const uint32_t* a,
                                      uint32_t b0, uint32_t b1) {
    asm volatile(
        "mma.sync.aligned.m16n8k16.row.col.f32.f16.f16.f32 "
        "{%0,%1,%2,%3}, {%4,%5,%6,%7}, {%8,%9}, {%0,%1,%2,%3};\n"
        : "+f"(d[0]), "+f"(d[1]), "+f"(d[2]), "+f"(d[3])
        : "r"(a[0]), "r"(a[1]), "r"(a[2]), "r"(a[3]), "r"(b0), "r"(b1));
}

__device__ __forceinline__ void ldsm4(uint32_t* r, uint32_t addr) {
    asm volatile("ldmatrix.sync.aligned.m8n8.x4.shared.b16 {%0,%1,%2,%3}, [%4];"
        : "=r"(r[0]), "=r"(r[1]), "=r"(r[2]), "=r"(r[3]) : "r"(addr));
}

__device__ __forceinline__ void ldsm4t(uint32_t* r, uint32_t addr) {
    asm volatile("ldmatrix.sync.aligned.m8n8.x4.trans.shared.b16 {%0,%1,%2,%3}, [%4];"
        : "=r"(r[0]), "=r"(r[1]), "=r"(r[2]), "=r"(r[3]) : "r"(addr));
}

__device__ __forceinline__ void ldsm2t(uint32_t* r, uint32_t addr) {
    asm volatile("ldmatrix.sync.aligned.m8n8.x2.trans.shared.b16 {%0,%1}, [%2];"
        : "=r"(r[0]), "=r"(r[1]) : "r"(addr));
}

__device__ __forceinline__ void cpasync16(uint32_t dst, const void* src) {
    asm volatile("cp.async.cg.shared.global [%0], [%1], 16;" :: "r"(dst), "l"(src));
}

__device__ __forceinline__ float exp2a(float x) {
    float y;
    asm("ex2.approx.f32 %0, %1;" : "=f"(y) : "f"(x));
    return y;
}

__device__ __forceinline__ uint32_t exp2h2(float a, float b) {
    half2 h = __floats2half2_rn(a, b);
    uint32_t u = *(uint32_t*)&h, y;
    asm("ex2.approx.f16x2 %0, %1;" : "=r"(y) : "r"(u));
    return y;
}

__device__ __forceinline__ void store2(float* p, float a, float b) {
    *(float2*)p = make_float2(a, b);
}
__device__ __forceinline__ void store2(__half* p, float a, float b) {
    *(half2*)p = __floats2half2_rn(a, b);
}

// ---------------- fused prep: weight fp16 conversion + adaLN modulation ----
__global__ void __launch_bounds__(256) prep_kernel(
    const float* __restrict__ wq, const float* __restrict__ wk,
    const float* __restrict__ wv, const float* __restrict__ wo,
    const float* __restrict__ w1, const float* __restrict__ w2,
    __half* __restrict__ rq, __half* __restrict__ rk,
    __half* __restrict__ rv, __half* __restrict__ ro,
    __half* __restrict__ r1, __half* __restrict__ r2,
    const float* __restrict__ cond,
    const float* __restrict__ wa1, const float* __restrict__ ba1,
    const float* __restrict__ wa2, const float* __restrict__ ba2,
    float* __restrict__ ss)
{
    if (blockIdx.x < 12288) {
        const int S = 262144; // 1M floats in float4 units
        int idx = blockIdx.x * 256 + threadIdx.x;  // 0 .. 3145727
        const float* s; __half* d; int off;
        if      (idx <     S) { s = wq; d = rq; off = idx; }
        else if (idx < 2 * S) { s = wk; d = rk; off = idx - S; }
        else if (idx < 3 * S) { s = wv; d = rv; off = idx - 2 * S; }
        else if (idx < 4 * S) { s = wo; d = ro; off = idx - 3 * S; }
        else if (idx < 8 * S) { s = w1; d = r1; off = idx - 4 * S; }
        else                  { s = w2; d = r2; off = idx - 8 * S; }
        float4 v = ((const float4*)s)[off];
        half2 h01 = __floats2half2_rn(v.x, v.y);
        half2 h23 = __floats2half2_rn(v.z, v.w);
        ((half2*)d)[off * 2]     = h01;
        ((half2*)d)[off * 2 + 1] = h23;
    } else {
        int warp = threadIdx.x >> 5, lane = threadIdx.x & 31;
        int gw = (blockIdx.x - 12288) * 8 + warp;  // 0..8191
        int layer = gw >> 12;
        int rem = gw & 4095;
        int b = rem >> 11;
        int row = rem & 2047;
        const float* W  = layer ? wa2 : wa1;
        const float* bv = layer ? ba2 : ba1;
        const float* c  = cond + b * CDIM;
        const float* wr = W + (size_t)row * CDIM;
        float s = 0.f;
        for (int k = lane; k < CDIM; k += 32) s += c[k] * wr[k];
        #pragma unroll
        for (int o = 16; o > 0; o >>= 1) s += __shfl_xor_sync(0xffffffffu, s, o);
        if (lane == 0) ss[layer * (BATCH * 2048) + b * 2048 + row] = s + bv[row];
    }
}

// ---------------- LayerNorm * (1+scale) + shift (output fp16) --------------
__global__ void __launch_bounds__(256) adaln_kernel(
    const float* __restrict__ x, const float* __restrict__ ss,
    __half* __restrict__ out)
{
    int row = blockIdx.x;
    int b = row >> 11;
    const float* xr = x + (size_t)row * HID;
    float v[4];
    float s = 0.f, sq = 0.f;
    #pragma unroll
    for (int i = 0; i < 4; i++) {
        v[i] = xr[threadIdx.x + i * 256];
        s += v[i];
        sq += v[i] * v[i];
    }
    __shared__ float red[16];
    #pragma unroll
    for (int o = 16; o > 0; o >>= 1) {
        s  += __shfl_xor_sync(0xffffffffu, s,  o);
        sq += __shfl_xor_sync(0xffffffffu, sq, o);
    }
    int warp = threadIdx.x >> 5, lane = threadIdx.x & 31;
    if (lane == 0) { red[warp] = s; red[warp + 8] = sq; }
    __syncthreads();
    if (warp == 0) {
        float a  = lane < 8 ? red[lane] : 0.f;
        float c2 = lane < 8 ? red[lane + 8] : 0.f;
        #pragma unroll
        for (int o = 4; o > 0; o >>= 1) {
            a  += __shfl_xor_sync(0xffffffffu, a,  o);
            c2 += __shfl_xor_sync(0xffffffffu, c2, o);
        }
        if (lane == 0) { red[0] = a; red[1] = c2; }
    }
    __syncthreads();
    float mean = red[0] * (1.f / HID);
    float var  = red[1] * (1.f / HID) - mean * mean;
    float rs   = rsqrtf(var + 1e-5f);
    const float* sc = ss + b * 2048;
    #pragma unroll
    for (int i = 0; i < 4; i++) {
        int c = threadIdx.x + i * 256;
        out[(size_t)row * HID + c] =
            __float2half_rn((v[i] - mean) * rs * (1.f + sc[c]) + sc[1024 + c]);
    }
}

// ---------------- pipelined FP16 GEMM: C = A @ B^T + bias (+resid)(gelu) ---
// R12-proven config: BM=128, BN=128, BK=64, 256 threads = 8 warps as 4x2,
// warp tile 32x64, 3-stage ring = 98 KB -> 2 CTAs/SM.
#define TBM 128
#define TBN 128
#define TBK 64
#define GSTAGES 3
#define STG_BYTES ((TBM + TBN) * 128)        // 32768
#define B_OFF (TBM * 128)                    // 16384
#define GSMEM (GSTAGES * STG_BYTES)          // 98304

template <bool GELU, bool RESID, bool QSC, typename OT>
__global__ void __launch_bounds__(256, 2) gemm2(
    const __half* __restrict__ A,
    const __half* __restrict__ Bp0, const __half* __restrict__ Bp1, const __half* __restrict__ Bp2,
    const float* __restrict__ bias0, const float* __restrict__ bias1, const float* __restrict__ bias2,
    const float* __restrict__ R,
    OT* __restrict__ C0, OT* __restrict__ C1, OT* __restrict__ C2,
    int M, int N, int K)
{
    extern __shared__ char smraw[];
    int which = blockIdx.z;
    const __half* B   = which == 0 ? Bp0   : (which == 1 ? Bp1   : Bp2);
    const float* bias = which == 0 ? bias0 : (which == 1 ? bias1 : bias2);
    OT*          C    = which == 0 ? C0    : (which == 1 ? C1    : C2);
    float osc = (QSC && which == 0) ? QSCALE_F : 1.f;

    int tid = threadIdx.x, warp = tid >> 5, lane = tid & 31;
    int bm = blockIdx.y * TBM, bn = blockIdx.x * TBN;
    int wm = (warp >> 1) * 32;   // 4 warp-rows of 32
    int wn = (warp & 1) * 64;    // 2 warp-cols of 64

    float acc[2][8][4];
    #pragma unroll
    for (int i = 0; i < 2; i++)
        #pragma unroll
        for (int j = 0; j < 8; j++)
            #pragma unroll
            for (int e = 0; e < 4; e++) acc[i][j][e] = 0.f;

    uint32_t smb = (uint32_t)__cvta_generic_to_shared(smraw);

    auto load_stage = [&](int slot, int k0) {
        uint32_t sb = smb + (uint32_t)slot * STG_BYTES;
        #pragma unroll
        for (int i = 0; i < 4; i++) {
            int idx = tid + i * 256;
            int r = idx >> 3, g = idx & 7;
            cpasync16(sb + (uint32_t)(r * 128 + ((g ^ (r & 7)) << 4)),
                      A + (size_t)(bm + r) * K + k0 + g * 8);
        }
        #pragma unroll
        for (int i = 0; i < 4; i++) {
            int idx = tid + i * 256;
            int r = idx >> 3, g = idx & 7;
            cpasync16(sb + B_OFF + (uint32_t)(r * 128 + ((g ^ (r & 7)) << 4)),
                      B + (size_t)(bn + r) * K + k0 + g * 8);
        }
    };

    auto compute_stage = [&](int s) {
        uint32_t base = smb + (uint32_t)s * STG_BYTES;
        #pragma unroll
        for (int ks = 0; ks < 4; ks++) {
            uint32_t a[2][4], b[4][4];
            #pragma unroll
            for (int mt = 0; mt < 2; mt++) {
                int arow = wm + mt * 16 + (lane & 15);
                int gA = ks * 2 + (lane >> 4);
                ldsm4(a[mt], base + (uint32_t)(arow * 128 + ((gA ^ (arow & 7)) << 4)));
            }
            #pragma unroll
            for (int p = 0; p < 4; p++) {
                int brow = wn + p * 16 + ((lane >> 4) << 3) + (lane & 7);
                int gB = ks * 2 + ((lane >> 3) & 1);
                ldsm4(b[p], base + B_OFF + (uint32_t)(brow * 128 + ((gB ^ (brow & 7)) << 4)));
            }
            #pragma unroll
            for (int p = 0; p < 4; p++) {
                #pragma unroll
                for (int mt = 0; mt < 2; mt++) {
                    mma16(acc[mt][2 * p],     a[mt], b[p][0], b[p][1]);
                    mma16(acc[mt][2 * p + 1], a[mt], b[p][2], b[p][3]);
                }
            }
        }
    };

    int KT = K / TBK;
    load_stage(0, 0);
    asm volatile("cp.async.commit_group;");
    load_stage(1, TBK);
    asm volatile("cp.async.commit_group;");

    for (int kt = 0; kt < KT; kt++) {
        asm volatile("cp.async.wait_group 1;");
        __syncthreads();
        if (kt + 2 < KT) load_stage((kt + 2) % GSTAGES, (kt + 2) * TBK);
        asm volatile("cp.async.commit_group;");
        compute_stage(kt % GSTAGES);
    }

    #pragma unroll
    for (int mt = 0; mt < 2; mt++) {
        int r0 = bm + wm + mt * 16 + (lane >> 2);
        #pragma unroll
        for (int nt = 0; nt < 8; nt++) {
            int cn = bn + wn + nt * 8 + (lane & 3) * 2;
            float b0 = bias[cn], b1 = bias[cn + 1];
            float v0 = acc[mt][nt][0] + b0;
            float v1 = acc[mt][nt][1] + b1;
            float v2 = acc[mt][nt][2] + b0;
            float v3 = acc[mt][nt][3] + b1;
            if (RESID) {
                v0 += R[(size_t)r0 * N + cn];
                v1 += R[(size_t)r0 * N + cn + 1];
                v2 += R[(size_t)(r0 + 8) * N + cn];
                v3 += R[(size_t)(r0 + 8) * N + cn + 1];
            }
            if (GELU) {
                v0 = 0.5f * v0 * (1.f + erff(v0 * 0.70710678118f));
                v1 = 0.5f * v1 * (1.f + erff(v1 * 0.70710678118f));
                v2 = 0.5f * v2 * (1.f + erff(v2 * 0.70710678118f));
                v3 = 0.5f * v3 * (1.f + erff(v3 * 0.70710678118f));
            }
            if (QSC) { v0 *= osc; v1 *= osc; v2 *= osc; v3 *= osc; }
            store2(C + (size_t)r0 * N + cn,       v0, v1);
            store2(C + (size_t)(r0 + 8) * N + cn, v2, v3);
        }
    }
}

// ---------------- fp16 flash attention --------------------------------------
// exp2 softmax (Q pre-scaled), register-resident P (f16x2 MUFU), row sums l
// computed BY the PV MMA via a ones-column at V col 64 (pad cols zeroed),
// alpha rescale skipped when running max unchanged.
// grid (L/128, NH, B). 256 threads = 8 warps, each warp owns 16 q rows.
#define KVT 64
#define NKB (LSEQ / KVT)     // 32
#define FSTR 72              // halves per row (64 + 8 pad) = 144B
#define FA_SMEM ((128 * FSTR + 2 * KVT * FSTR + 2 * KVT * FSTR) * 2 + 2 * KVT * 4)

__global__ void __launch_bounds__(256, 2) flash_kernel(
    const __half* __restrict__ Q, const __half* __restrict__ Kb,
    const __half* __restrict__ Vb, const unsigned char* __restrict__ msk,
    __half* __restrict__ O)
{
    extern __shared__ char fsm[];
    __half* Qs = (__half*)fsm;                 // [128][72]
    __half* Ks = Qs + 128 * FSTR;              // [2][64][72]
    __half* Vs = Ks + 2 * KVT * FSTR;          // [2][64][72]
    float*  Mb = (float*)(Vs + 2 * KVT * FSTR);// [2][64]
    uint32_t qs_b = (uint32_t)__cvta_generic_to_shared(Qs);
    uint32_t ks_b = (uint32_t)__cvta_generic_to_shared(Ks);
    uint32_t vs_b = (uint32_t)__cvta_generic_to_shared(Vs);

    int qb = blockIdx.x, h = blockIdx.y, b = blockIdx.z;
    int tid = threadIdx.x, warp = tid >> 5, lane = tid & 31;

    size_t base_q = ((size_t)(b * LSEQ + qb * 128)) * HID + h * HDIM;
    #pragma unroll
    for (int i = 0; i < 4; i++) {
        int idx = tid + i * 256;
        int r = idx >> 3, g = idx & 7;
        cpasync16(qs_b + (uint32_t)(r * 144 + g * 16),
                  Q + base_q + (size_t)r * HID + g * 8);
    }
    // V pad init: col 64 = 1.0 (ones column for row-sum MMA), cols 65-71 = 0.
    // cp.async only ever writes cols 0-63, so this persists across tiles.
    if (tid < 128) {
        __half* row = Vs + tid * FSTR + 64;   // covers both buffers (128 rows)
        *(uint4*)row = make_uint4(0x00003c00u, 0u, 0u, 0u);
    }

    auto load_kv = [&](int kb, int buf) {
        size_t base_k = ((size_t)(b * LSEQ + kb * KVT)) * HID + h * HDIM;
        uint32_t boff = (uint32_t)(buf * KVT * 144);
        #pragma unroll
        for (int i = 0; i < 2; i++) {
            int idx = tid + i * 256;
            int r = idx >> 3, g = idx & 7;
            uint32_t so = (uint32_t)(r * 144 + g * 16);
            cpasync16(ks_b + boff + so, Kb + base_k + (size_t)r * HID + g * 8);
            cpasync16(vs_b + boff + so, Vb + base_k + (size_t)r * HID + g * 8);
        }
        if (tid < KVT)
            Mb[buf * KVT + tid] = msk[b * LSEQ + kb * KVT + tid] ? -1e30f : 0.f;
    };

    load_kv(0, 0);
    asm volatile("cp.async.commit_group;");

    float Oacc[8][4];
    #pragma unroll
    for (int i = 0; i < 8; i++)
        #pragma unroll
        for (int e = 0; e < 4; e++) Oacc[i][e] = 0.f;
    float lacc[4] = {0.f, 0.f, 0.f, 0.f};     // row-sum accumulator (col 64)
    float m0 = -1e30f, m1 = -1e30f;

    for (int kb = 0; kb < NKB; kb++) {
        int cur = kb & 1;
        asm volatile("cp.async.wait_group 0;");
        __syncthreads();
        if (kb + 1 < NKB) {
            load_kv(kb + 1, cur ^ 1);
            asm volatile("cp.async.commit_group;");
        }
        uint32_t kbuf = ks_b + (uint32_t)(cur * KVT * 144);
        uint32_t vbuf = vs_b + (uint32_t)(cur * KVT * 144);
        const float* mb = Mb + cur * KVT;

        // S = Q @ K^T  (exp2-domain; Q pre-scaled)
        float sacc[8][4];
        #pragma unroll
        for (int i = 0; i < 8; i++)
            #pragma unroll
            for (int e = 0; e < 4; e++) sacc[i][e] = 0.f;

        #pragma unroll
        for (int ks = 0; ks < 4; ks++) {
            uint32_t af[4];
            int arow = warp * 16 + (lane & 15);
            ldsm4(af, qs_b + (uint32_t)(arow * 144 + ks * 32 + (lane >> 4) * 16));
            #pragma unroll
            for (int nt2 = 0; nt2 < 4; nt2++) {
                uint32_t bf[4];
                int brow = nt2 * 16 + ((lane >> 4) << 3) + (lane & 7);
                ldsm4(bf, kbuf + (uint32_t)(brow * 144 + ks * 32 + ((lane >> 3) & 1) * 16));
                mma16(sacc[nt2 * 2],     af, bf[0], bf[1]);
                mma16(sacc[nt2 * 2 + 1], af, bf[2], bf[3]);
            }
        }

        // mask + both-row max in one pass
        float2 mk[8];
        #pragma unroll
        for (int nt = 0; nt < 8; nt++)
            mk[nt] = *(const float2*)&mb[nt * 8 + (lane & 3) * 2];

        float t0 = -1e30f, t1 = -1e30f;
        #pragma unroll
        for (int nt = 0; nt < 8; nt++) {
            float s0 = sacc[nt][0] + mk[nt].x;
            float s1 = sacc[nt][1] + mk[nt].y;
            float s2 = sacc[nt][2] + mk[nt].x;
            float s3 = sacc[nt][3] + mk[nt].y;
            sacc[nt][0] = s0; sacc[nt][1] = s1;
            sacc[nt][2] = s2; sacc[nt][3] = s3;
            t0 = fmaxf(t0, fmaxf(s0, s1));
            t1 = fmaxf(t1, fmaxf(s2, s3));
        }
        t0 = fmaxf(t0, __shfl_xor_sync(0xffffffffu, t0, 1));
        t0 = fmaxf(t0, __shfl_xor_sync(0xffffffffu, t0, 2));
        t1 = fmaxf(t1, __shfl_xor_sync(0xffffffffu, t1, 1));
        t1 = fmaxf(t1, __shfl_xor_sync(0xffffffffu, t1, 2));
        float mn0 = fmaxf(m0, t0), mn1 = fmaxf(m1, t1);

        // rescale only when the running max moved (common case after warmup: no)
        if (mn0 != m0 || mn1 != m1) {
            float al0 = exp2a(m0 - mn0), al1 = exp2a(m1 - mn1);
            m0 = mn0; m1 = mn1;
            #pragma unroll
            for (int nt = 0; nt < 8; nt++) {
                Oacc[nt][0] *= al0; Oacc[nt][1] *= al0;
                Oacc[nt][2] *= al1; Oacc[nt][3] *= al1;
            }
            lacc[0] *= al0; lacc[1] *= al0;
            lacc[2] *= al1; lacc[3] *= al1;
        }

        // exp2 (f16x2 MUFU) -> P directly in PV A-fragments (registers)
        uint32_t pa[4][4];
        #pragma unroll
        for (int t = 0; t < 4; t++) {
            pa[t][0] = exp2h2(sacc[2 * t][0] - m0,     sacc[2 * t][1] - m0);
            pa[t][1] = exp2h2(sacc[2 * t][2] - m1,     sacc[2 * t][3] - m1);
            pa[t][2] = exp2h2(sacc[2 * t + 1][0] - m0, sacc[2 * t + 1][1] - m0);
            pa[t][3] = exp2h2(sacc[2 * t + 1][2] - m1, sacc[2 * t + 1][3] - m1);
        }

        // O += P @ V; l += P @ ones (V col 64)
        #pragma unroll
        for (int ks = 0; ks < 4; ks++) {
            #pragma unroll
            for (int nt2 = 0; nt2 < 4; nt2++) {
                uint32_t bf[4];
                int vrow = ks * 16 + ((lane >> 3) & 1) * 8 + (lane & 7);
                ldsm4t(bf, vbuf + (uint32_t)(vrow * 144 + nt2 * 32 + (lane >> 4) * 16));
                mma16(Oacc[nt2 * 2],     pa[ks], bf[0], bf[1]);
                mma16(Oacc[nt2 * 2 + 1], pa[ks], bf[2], bf[3]);
            }
            {
                uint32_t bl[2];
                int vrow = ks * 16 + ((lane >> 3) & 1) * 8 + (lane & 7);
                ldsm2t(bl, vbuf + (uint32_t)(vrow * 144 + 128));
                mma16(lacc, pa[ks], bl[0], bl[1]);
            }
        }
    }

    {
        // row sum lives in col 64 -> lane with (lane&3)==0 of each 4-lane group
        float l0 = __shfl_sync(0xffffffffu, lacc[0], lane & ~3);
        float l1 = __shfl_sync(0xffffffffu, lacc[2], lane & ~3);
        float inv0 = 1.f / l0, inv1 = 1.f / l1;
        int row = qb * 128 + warp * 16 + (lane >> 2);
        size_t ob0 = ((size_t)(b * LSEQ + row)) * HID + h * HDIM;
        size_t ob1 = ((size_t)(b * LSEQ + row + 8)) * HID + h * HDIM;
        #pragma unroll
        for (int nt = 0; nt < 8; nt++) {
            int cc = nt * 8 + (lane & 3) * 2;
            *(half2*)&O[ob0 + cc] =
                __floats2half2_rn(Oacc[nt][0] * inv0, Oacc[nt][1] * inv0);
            *(half2*)&O[ob1 + cc] =
                __floats2half2_rn(Oacc[nt][2] * inv1, Oacc[nt][3] * inv1);
        }
    }
}

// ---------------- launch ----------------------------------------------------
extern "C" void kernel_launch(void* const* d_in, const int* in_sizes, int n_in,
                              void* d_out, int out_size)
{
    const float* x    = (const float*)d_in[0];
    const float* cond = (const float*)d_in[1];
    const unsigned char* kpm = (const unsigned char*)d_in[2];
    const float* w_ad1 = (const float*)d_in[3];
    const float* b_ad1 = (const float*)d_in[4];
    const float* w_ad2 = (const float*)d_in[5];
    const float* b_ad2 = (const float*)d_in[6];
    const float* wq = (const float*)d_in[7];
    const float* bq = (const float*)d_in[8];
    const float* wk = (const float*)d_in[9];
    const float* bk = (const float*)d_in[10];
    const float* wv = (const float*)d_in[11];
    const float* bv = (const float*)d_in[12];
    const float* wo = (const float*)d_in[13];
    const float* bo = (const float*)d_in[14];
    const float* w1 = (const float*)d_in[15];
    const float* b1 = (const float*)d_in[16];
    const float* w2 = (const float*)d_in[17];
    const float* b2 = (const float*)d_in[18];
    float* out = (float*)d_out;

    __half *p_normed, *p_q, *p_k, *p_v, *p_attn, *p_h;
    __half *p_rwq, *p_rwk, *p_rwv, *p_rwo, *p_rw1, *p_rw2;
    float *p_ss;
    cudaGetSymbolAddress((void**)&p_normed, g_normed);
    cudaGetSymbolAddress((void**)&p_q,    g_q);
    cudaGetSymbolAddress((void**)&p_k,    g_k);
    cudaGetSymbolAddress((void**)&p_v,    g_v);
    cudaGetSymbolAddress((void**)&p_attn, g_attn);
    cudaGetSymbolAddress((void**)&p_h,    g_h);
    cudaGetSymbolAddress((void**)&p_ss,   g_ss);
    cudaGetSymbolAddress((void**)&p_rwq,  g_rwq);
    cudaGetSymbolAddress((void**)&p_rwk,  g_rwk);
    cudaGetSymbolAddress((void**)&p_rwv,  g_rwv);
    cudaGetSymbolAddress((void**)&p_rwo,  g_rwo);
    cudaGetSymbolAddress((void**)&p_rw1,  g_rw1);
    cudaGetSymbolAddress((void**)&p_rw2,  g_rw2);

    cudaFuncSetAttribute(flash_kernel,
                         cudaFuncAttributeMaxDynamicSharedMemorySize, FA_SMEM);
    cudaFuncSetAttribute(gemm2<false, false, true, __half>,
                         cudaFuncAttributeMaxDynamicSharedMemorySize, GSMEM);
    cudaFuncSetAttribute(gemm2<false, true, false, float>,
                         cudaFuncAttributeMaxDynamicSharedMemorySize, GSMEM);
    cudaFuncSetAttribute(gemm2<true, false, false, __half>,
                         cudaFuncAttributeMaxDynamicSharedMemorySize, GSMEM);

    // 0. weight conversion + adaLN modulation (merged)
    prep_kernel<<<13312, 256>>>(wq, wk, wv, wo, w1, w2,
                                p_rwq, p_rwk, p_rwv, p_rwo, p_rw1, p_rw2,
                                cond, w_ad1, b_ad1, w_ad2, b_ad2, p_ss);
    // 1. normed1 = LN(x) * (1+scale1) + shift1  (fp16)
    adaln_kernel<<<MTOT, 256>>>(x, p_ss, p_normed);
    // 2. fused q, k, v projections (fp16 out; Q pre-scaled for exp2 softmax)
    gemm2<false, false, true, __half><<<dim3(HID / TBN, MTOT / TBM, 3), 256, GSMEM>>>(
        p_normed, p_rwq, p_rwk, p_rwv, bq, bk, bv, nullptr,
        p_q, p_k, p_v, MTOT, HID, HID);
    // 3. attention (fp16 in/out; register-resident P; MMA row sums)
    flash_kernel<<<dim3(LSEQ / 128, NHEAD, BATCH), 256, FA_SMEM>>>(
        p_q, p_k, p_v, kpm, p_attn);
    // 4. x1 = x + attn @ wo^T + bo   (fp32, into d_out)
    gemm2<false, true, false, float><<<dim3(HID / TBN, MTOT / TBM, 1), 256, GSMEM>>>(
        p_attn, p_rwo, p_rwo, p_rwo, bo, bo, bo, x,
        out, out, out, MTOT, HID, HID);
    // 5. normed2 = LN(x1) * (1+scale2) + shift2  (fp16)
    adaln_kernel<<<MTOT, 256>>>(out, p_ss + BATCH * 2048, p_normed);
    // 6. h = gelu(normed2 @ w1^T + b1)  (fp16 out)
    gemm2<true, false, false, __half><<<dim3(MLPD / TBN, MTOT / TBM, 1), 256, GSMEM>>>(
        p_normed, p_rw1, p_rw1, p_rw1, b1, b1, b1, nullptr,
        p_h, p_h, p_h, MTOT, MLPD, HID);
    // 7. out = x1 + h @ w2^T + b2   (fp32, in-place on d_out)
    gemm2<false, true, false, float><<<dim3(HID / TBN, MTOT / TBM, 1), 256, GSMEM>>>(
        p_h, p_rw2, p_rw2, p_rw2, b2, b2, b2, out,
        out, out, out, MTOT, HID, MLPD);
}